// round 1
// baseline (speedup 1.0000x reference)
#include <cuda_runtime.h>
#include <math.h>

// ---------------------------------------------------------------------------
// Problem constants (fixed-shape problem instance)
//   x:      [4, 2048, 2048]  -> T = 8192 tokens, d = 2048
//   base_W: [2048, 2048]     (d_out x d_in, row-major, contraction on fast axis)
//   base_b: [2048]
//   A:      [16, 16, 2048]   (E, r, d_in)
//   B:      [16, 2048, 16]   (E, d_out, r)
//   gate_v: [16, 2048]
//   alphas: [16]
//   top_k = 2
// ---------------------------------------------------------------------------

#define D_IN   2048
#define D_OUT  2048
#define N_EXP  16
#define RANK   16
#define T_MAX  8192
#define EPSV   1e-6f

// Scratch (static device memory -- no allocation)
__device__ float g_gnorm[N_EXP];              // ||gate_v_e|| + EPS
__device__ int   g_idx[T_MAX * 2];            // top-2 expert ids per token
__device__ float g_w[T_MAX * 2];              // softmax weight * alpha / r
__device__ float g_mid[T_MAX * 2 * RANK];     // A_e @ x per (token, k)

// ---------------------------------------------------------------------------
// Kernel 1: gate vector norms
// ---------------------------------------------------------------------------
__global__ void gnorm_kernel(const float* __restrict__ gv) {
    int e = blockIdx.x;
    float s = 0.f;
    for (int j = threadIdx.x; j < D_IN; j += 256) {
        float v = gv[e * D_IN + j];
        s += v * v;
    }
    __shared__ float red[256];
    red[threadIdx.x] = s;
    __syncthreads();
    for (int st = 128; st > 0; st >>= 1) {
        if (threadIdx.x < st) red[threadIdx.x] += red[threadIdx.x + st];
        __syncthreads();
    }
    if (threadIdx.x == 0) g_gnorm[e] = sqrtf(red[0]) + EPSV;
}

// ---------------------------------------------------------------------------
// Kernel 2: routing. One block per token.
//   score[e] = (x . gv_e) / ((||x||+eps)(||gv_e||+eps) sqrt(d))
//   top-2 -> softmax -> fold alpha/r
// ---------------------------------------------------------------------------
__global__ void route_kernel(const float* __restrict__ x,
                             const float* __restrict__ gv,
                             const float* __restrict__ alphas) {
    int t = blockIdx.x;
    const float* xr = x + (size_t)t * D_IN;

    float xx = 0.f;
    float s[N_EXP];
#pragma unroll
    for (int e = 0; e < N_EXP; e++) s[e] = 0.f;

    for (int j = threadIdx.x; j < D_IN; j += 256) {
        float xv = xr[j];
        xx += xv * xv;
#pragma unroll
        for (int e = 0; e < N_EXP; e++)
            s[e] += xv * gv[e * D_IN + j];
    }

    // warp reduce 17 values
#pragma unroll
    for (int off = 16; off > 0; off >>= 1) {
        xx += __shfl_down_sync(0xFFFFFFFFu, xx, off);
#pragma unroll
        for (int e = 0; e < N_EXP; e++)
            s[e] += __shfl_down_sync(0xFFFFFFFFu, s[e], off);
    }

    __shared__ float sm[8][N_EXP + 1];
    int w = threadIdx.x >> 5, l = threadIdx.x & 31;
    if (l == 0) {
        sm[w][0] = xx;
#pragma unroll
        for (int e = 0; e < N_EXP; e++) sm[w][e + 1] = s[e];
    }
    __syncthreads();

    if (threadIdx.x == 0) {
        float fxx = 0.f;
        float fs[N_EXP];
#pragma unroll
        for (int e = 0; e < N_EXP; e++) fs[e] = 0.f;
        for (int ww = 0; ww < 8; ww++) {
            fxx += sm[ww][0];
#pragma unroll
            for (int e = 0; e < N_EXP; e++) fs[e] += sm[ww][e + 1];
        }
        float inv = 1.f / ((sqrtf(fxx) + EPSV) * sqrtf((float)D_IN));
        float sc[N_EXP];
#pragma unroll
        for (int e = 0; e < N_EXP; e++) sc[e] = fs[e] * inv / g_gnorm[e];

        // top-2 (lowest index wins ties, matching jax.lax.top_k)
        int i0 = 0;
#pragma unroll
        for (int e = 1; e < N_EXP; e++) if (sc[e] > sc[i0]) i0 = e;
        int i1 = (i0 == 0) ? 1 : 0;
#pragma unroll
        for (int e = 0; e < N_EXP; e++)
            if (e != i0 && sc[e] > sc[i1]) i1 = e;

        float dlt = sc[i1] - sc[i0];       // <= 0
        float e1 = expf(dlt);
        float denom = 1.f + e1;
        float w0 = 1.f / denom;
        float w1 = e1 / denom;

        g_idx[t * 2 + 0] = i0;
        g_idx[t * 2 + 1] = i1;
        g_w[t * 2 + 0] = w0 * alphas[i0] * (1.f / (float)RANK);
        g_w[t * 2 + 1] = w1 * alphas[i1] * (1.f / (float)RANK);
    }
}

// ---------------------------------------------------------------------------
// Kernel 3: mid[t,k,r] = A[e_k, r, :] . x[t, :]
// grid (T, 2), 512 threads = 16 warps, warp w computes rank row w.
// ---------------------------------------------------------------------------
__global__ void mid_kernel(const float* __restrict__ x,
                           const float* __restrict__ A) {
    int t = blockIdx.x;
    int k = blockIdx.y;
    int e = g_idx[t * 2 + k];
    int w = threadIdx.x >> 5, l = threadIdx.x & 31;

    const float* xr = x + (size_t)t * D_IN;
    const float* ar = A + ((size_t)e * RANK + w) * D_IN;

    float acc = 0.f;
    for (int j = l; j < D_IN; j += 32)
        acc += xr[j] * ar[j];
#pragma unroll
    for (int off = 16; off > 0; off >>= 1)
        acc += __shfl_down_sync(0xFFFFFFFFu, acc, off);
    if (l == 0) g_mid[((size_t)t * 2 + k) * RANK + w] = acc;
}

// ---------------------------------------------------------------------------
// Kernel 4: out[t, o] = bias[o] + sum_k w_k * (B[e_k, o, :] . mid[t, k, :])
// One block per token, 256 threads.
// ---------------------------------------------------------------------------
__global__ void lora_kernel(const float* __restrict__ B,
                            const float* __restrict__ bias,
                            float* __restrict__ out) {
    int t = blockIdx.x;
    __shared__ float mids[32];
    __shared__ int   eidx[2];
    __shared__ float wv[2];
    if (threadIdx.x < 32) mids[threadIdx.x] = g_mid[(size_t)t * 32 + threadIdx.x];
    if (threadIdx.x < 2) {
        eidx[threadIdx.x] = g_idx[t * 2 + threadIdx.x];
        wv[threadIdx.x]   = g_w[t * 2 + threadIdx.x];
    }
    __syncthreads();

    const float* B0 = B + (size_t)eidx[0] * D_OUT * RANK;
    const float* B1 = B + (size_t)eidx[1] * D_OUT * RANK;
    float w0 = wv[0], w1 = wv[1];
    float m0[RANK], m1[RANK];
#pragma unroll
    for (int r = 0; r < RANK; r++) { m0[r] = mids[r]; m1[r] = mids[RANK + r]; }

    for (int o = threadIdx.x; o < D_OUT; o += 256) {
        const float4* b0 = (const float4*)(B0 + (size_t)o * RANK);
        const float4* b1 = (const float4*)(B1 + (size_t)o * RANK);
        float a0 = 0.f, a1 = 0.f;
#pragma unroll
        for (int q = 0; q < 4; q++) {
            float4 v0 = b0[q];
            float4 v1 = b1[q];
            a0 += v0.x * m0[q * 4 + 0] + v0.y * m0[q * 4 + 1]
                + v0.z * m0[q * 4 + 2] + v0.w * m0[q * 4 + 3];
            a1 += v1.x * m1[q * 4 + 0] + v1.y * m1[q * 4 + 1]
                + v1.z * m1[q * 4 + 2] + v1.w * m1[q * 4 + 3];
        }
        out[(size_t)t * D_OUT + o] = bias[o] + w0 * a0 + w1 * a1;
    }
}

// ---------------------------------------------------------------------------
// Kernel 5: SGEMM  out[t, o] += X[t, :] . W[o, :]
// 128x128 tile, BK=16, 256 threads, 8x8 micro-tile (two 4-wide chunks
// separated by 64 in each dim for conflict-free float4 smem reads).
// ---------------------------------------------------------------------------
#define BM 128
#define BN 128
#define BK 16

__global__ void __launch_bounds__(256, 2)
gemm_kernel(const float* __restrict__ X,
            const float* __restrict__ W,
            float* __restrict__ out) {
    __shared__ float Xs[BK][BM];
    __shared__ float Ws[BK][BN];

    const int bt = blockIdx.y * BM;
    const int bo = blockIdx.x * BN;
    const int tid = threadIdx.x;
    const int tr = tid >> 4;   // 0..15
    const int tc = tid & 15;   // 0..15

    float acc[8][8];
#pragma unroll
    for (int i = 0; i < 8; i++)
#pragma unroll
        for (int j = 0; j < 8; j++) acc[i][j] = 0.f;

    for (int kk = 0; kk < D_IN; kk += BK) {
        // cooperative load: 512 float4 slots per matrix, 2 per thread
#pragma unroll
        for (int i = 0; i < 2; i++) {
            int slot = tid + i * 256;
            int row = slot >> 2;
            int c4  = (slot & 3) << 2;
            float4 xv = *(const float4*)(X + (size_t)(bt + row) * D_IN + kk + c4);
            Xs[c4 + 0][row] = xv.x;
            Xs[c4 + 1][row] = xv.y;
            Xs[c4 + 2][row] = xv.z;
            Xs[c4 + 3][row] = xv.w;
            float4 wv = *(const float4*)(W + (size_t)(bo + row) * D_IN + kk + c4);
            Ws[c4 + 0][row] = wv.x;
            Ws[c4 + 1][row] = wv.y;
            Ws[c4 + 2][row] = wv.z;
            Ws[c4 + 3][row] = wv.w;
        }
        __syncthreads();

#pragma unroll
        for (int k = 0; k < BK; k++) {
            float xr[8], wr[8];
            *(float4*)&xr[0] = *(const float4*)&Xs[k][tr * 4];
            *(float4*)&xr[4] = *(const float4*)&Xs[k][tr * 4 + 64];
            *(float4*)&wr[0] = *(const float4*)&Ws[k][tc * 4];
            *(float4*)&wr[4] = *(const float4*)&Ws[k][tc * 4 + 64];
#pragma unroll
            for (int i = 0; i < 8; i++)
#pragma unroll
                for (int j = 0; j < 8; j++)
                    acc[i][j] += xr[i] * wr[j];
        }
        __syncthreads();
    }

    // epilogue: out += acc (out already holds bias + LoRA contribution)
#pragma unroll
    for (int i = 0; i < 8; i++) {
        int m = bt + tr * 4 + ((i < 4) ? i : (64 + i - 4));
#pragma unroll
        for (int jq = 0; jq < 2; jq++) {
            int n = bo + tc * 4 + jq * 64;
            float4* p = (float4*)(out + (size_t)m * D_OUT + n);
            float4 v = *p;
            v.x += acc[i][jq * 4 + 0];
            v.y += acc[i][jq * 4 + 1];
            v.z += acc[i][jq * 4 + 2];
            v.w += acc[i][jq * 4 + 3];
            *p = v;
        }
    }
}

// ---------------------------------------------------------------------------
// Launch
// ---------------------------------------------------------------------------
extern "C" void kernel_launch(void* const* d_in, const int* in_sizes, int n_in,
                              void* d_out, int out_size) {
    const float* x  = (const float*)d_in[0];
    const float* Wm = (const float*)d_in[1];
    const float* bb = (const float*)d_in[2];
    const float* A  = (const float*)d_in[3];
    const float* B  = (const float*)d_in[4];
    const float* gv = (const float*)d_in[5];
    const float* al = (const float*)d_in[6];
    float* out = (float*)d_out;

    int T = in_sizes[0] / D_IN;   // 8192

    gnorm_kernel<<<N_EXP, 256>>>(gv);
    route_kernel<<<T, 256>>>(x, gv, al);
    mid_kernel<<<dim3(T, 2), 512>>>(x, A);
    lora_kernel<<<T, 256>>>(B, bb, out);
    gemm_kernel<<<dim3(D_OUT / BN, T / BM), 256>>>(x, Wm, out);
}

// round 3
// speedup vs baseline: 1.3331x; 1.3331x over previous
#include <cuda_runtime.h>
#include <cuda_bf16.h>
#include <math.h>
#include <stdint.h>

// ---------------------------------------------------------------------------
// Shapes (fixed):
//   x [4,2048,2048] -> T=8192, d=2048 ; base_W [2048,2048]; base_b [2048]
//   A [16,16,2048]; B [16,2048,16]; gate_v [16,2048]; alphas[16]; top_k=2
// ---------------------------------------------------------------------------

#define D_IN   2048
#define D_OUT  2048
#define N_EXP  16
#define RANK   16
#define T_MAX  8192
#define EPSV   1e-6f

// Scratch (static device memory -- no allocation)
__device__ float g_gnorm[N_EXP];
__device__ int   g_idx[T_MAX * 2];
__device__ float g_w[T_MAX * 2];
__device__ float g_mid[T_MAX * 2 * RANK];

// bf16 hi/lo split operands for tensor-core GEMM
__device__ __nv_bfloat16 g_Xhi[(size_t)T_MAX * D_IN];
__device__ __nv_bfloat16 g_Xlo[(size_t)T_MAX * D_IN];
__device__ __nv_bfloat16 g_Whi[(size_t)D_OUT * D_IN];
__device__ __nv_bfloat16 g_Wlo[(size_t)D_OUT * D_IN];

// ---------------------------------------------------------------------------
// PTX helpers (sm_80-era only: cp.async, ldmatrix, mma.sync)
// ---------------------------------------------------------------------------
__device__ __forceinline__ uint32_t smem_u32(const void* p) {
    uint32_t a;
    asm("{ .reg .u64 t; cvta.to.shared.u64 t, %1; cvt.u32.u64 %0, t; }"
        : "=r"(a) : "l"(p));
    return a;
}
__device__ __forceinline__ void cp16(uint32_t dst, const void* src) {
    asm volatile("cp.async.cg.shared.global [%0], [%1], 16;" :: "r"(dst), "l"(src));
}
__device__ __forceinline__ void ldsm_x4(uint32_t* r, uint32_t addr) {
    asm volatile("ldmatrix.sync.aligned.m8n8.x4.shared.b16 {%0,%1,%2,%3}, [%4];"
                 : "=r"(r[0]), "=r"(r[1]), "=r"(r[2]), "=r"(r[3]) : "r"(addr));
}
#define MMA16816(cd, af, b0, b1)                                           \
    asm volatile("mma.sync.aligned.m16n8k16.row.col.f32.bf16.bf16.f32 "    \
                 "{%0,%1,%2,%3}, {%4,%5,%6,%7}, {%8,%9}, {%0,%1,%2,%3};"   \
                 : "+f"((cd)[0]), "+f"((cd)[1]), "+f"((cd)[2]), "+f"((cd)[3]) \
                 : "r"((af)[0]), "r"((af)[1]), "r"((af)[2]), "r"((af)[3]), \
                   "r"(b0), "r"(b1))

// ---------------------------------------------------------------------------
// Kernel: fp32 -> (hi,lo) bf16 split
// ---------------------------------------------------------------------------
__global__ void conv_split_kernel(const float* __restrict__ src,
                                  __nv_bfloat16* __restrict__ hi,
                                  __nv_bfloat16* __restrict__ lo,
                                  int n4) {
    int i = blockIdx.x * blockDim.x + threadIdx.x;
    if (i >= n4) return;
    float4 v = ((const float4*)src)[i];
    __nv_bfloat16 hx = __float2bfloat16(v.x);
    __nv_bfloat16 hy = __float2bfloat16(v.y);
    __nv_bfloat16 hz = __float2bfloat16(v.z);
    __nv_bfloat16 hw = __float2bfloat16(v.w);
    __nv_bfloat162* hp = (__nv_bfloat162*)hi;
    __nv_bfloat162* lp = (__nv_bfloat162*)lo;
    hp[2 * i + 0] = __nv_bfloat162(hx, hy);
    hp[2 * i + 1] = __nv_bfloat162(hz, hw);
    lp[2 * i + 0] = __nv_bfloat162(__float2bfloat16(v.x - __bfloat162float(hx)),
                                   __float2bfloat16(v.y - __bfloat162float(hy)));
    lp[2 * i + 1] = __nv_bfloat162(__float2bfloat16(v.z - __bfloat162float(hz)),
                                   __float2bfloat16(v.w - __bfloat162float(hw)));
}

// ---------------------------------------------------------------------------
// Kernel: gate vector norms
// ---------------------------------------------------------------------------
__global__ void gnorm_kernel(const float* __restrict__ gv) {
    int e = blockIdx.x;
    float s = 0.f;
    for (int j = threadIdx.x; j < D_IN; j += 256) {
        float v = gv[e * D_IN + j];
        s += v * v;
    }
    __shared__ float red[256];
    red[threadIdx.x] = s;
    __syncthreads();
    for (int st = 128; st > 0; st >>= 1) {
        if (threadIdx.x < st) red[threadIdx.x] += red[threadIdx.x + st];
        __syncthreads();
    }
    if (threadIdx.x == 0) g_gnorm[e] = sqrtf(red[0]) + EPSV;
}

// ---------------------------------------------------------------------------
// Kernel: routing (top-2 + softmax, fold alpha/r)
// ---------------------------------------------------------------------------
__global__ void route_kernel(const float* __restrict__ x,
                             const float* __restrict__ gv,
                             const float* __restrict__ alphas) {
    int t = blockIdx.x;
    const float* xr = x + (size_t)t * D_IN;

    float xx = 0.f;
    float s[N_EXP];
#pragma unroll
    for (int e = 0; e < N_EXP; e++) s[e] = 0.f;

    for (int j = threadIdx.x; j < D_IN; j += 256) {
        float xv = xr[j];
        xx += xv * xv;
#pragma unroll
        for (int e = 0; e < N_EXP; e++)
            s[e] += xv * gv[e * D_IN + j];
    }
#pragma unroll
    for (int off = 16; off > 0; off >>= 1) {
        xx += __shfl_down_sync(0xFFFFFFFFu, xx, off);
#pragma unroll
        for (int e = 0; e < N_EXP; e++)
            s[e] += __shfl_down_sync(0xFFFFFFFFu, s[e], off);
    }
    __shared__ float sm[8][N_EXP + 1];
    int w = threadIdx.x >> 5, l = threadIdx.x & 31;
    if (l == 0) {
        sm[w][0] = xx;
#pragma unroll
        for (int e = 0; e < N_EXP; e++) sm[w][e + 1] = s[e];
    }
    __syncthreads();
    if (threadIdx.x == 0) {
        float fxx = 0.f;
        float fs[N_EXP];
#pragma unroll
        for (int e = 0; e < N_EXP; e++) fs[e] = 0.f;
        for (int ww = 0; ww < 8; ww++) {
            fxx += sm[ww][0];
#pragma unroll
            for (int e = 0; e < N_EXP; e++) fs[e] += sm[ww][e + 1];
        }
        float inv = 1.f / ((sqrtf(fxx) + EPSV) * sqrtf((float)D_IN));
        float sc[N_EXP];
#pragma unroll
        for (int e = 0; e < N_EXP; e++) sc[e] = fs[e] * inv / g_gnorm[e];

        int i0 = 0;
#pragma unroll
        for (int e = 1; e < N_EXP; e++) if (sc[e] > sc[i0]) i0 = e;
        int i1 = (i0 == 0) ? 1 : 0;
#pragma unroll
        for (int e = 0; e < N_EXP; e++)
            if (e != i0 && sc[e] > sc[i1]) i1 = e;

        float e1 = expf(sc[i1] - sc[i0]);
        float denom = 1.f + e1;
        g_idx[t * 2 + 0] = i0;
        g_idx[t * 2 + 1] = i1;
        g_w[t * 2 + 0] = (1.f / denom) * alphas[i0] * (1.f / (float)RANK);
        g_w[t * 2 + 1] = (e1 / denom) * alphas[i1] * (1.f / (float)RANK);
    }
}

// ---------------------------------------------------------------------------
// Kernel: mid[t,k,r] = A[e_k, r, :] . x[t, :]
// 32 tokens per block (amortizes A reads across tokens), x staged in smem.
// 256 threads = 8 warps; each warp handles 8 (token,k) pairs; within a warp
// lane = (r = lane>>1, half = lane&1) accumulates 64-element strips.
// ---------------------------------------------------------------------------
__global__ void __launch_bounds__(256)
mid_kernel(const float* __restrict__ x, const float* __restrict__ A) {
    __shared__ float xs[32][128];
    const int t0 = blockIdx.x * 32;
    const int tid = threadIdx.x;
    const int w = tid >> 5, l = tid & 31;
    const int r = l >> 1, half = l & 1;

    float acc[8];
#pragma unroll
    for (int p = 0; p < 8; p++) acc[p] = 0.f;

    for (int kc = 0; kc < D_IN; kc += 128) {
        // stage x[t0..t0+31][kc..kc+127] into smem (1024 float4, 4/thread)
#pragma unroll
        for (int i = 0; i < 4; i++) {
            int f4 = tid + i * 256;
            int row = f4 >> 5, c4 = f4 & 31;
            ((float4*)&xs[row][0])[c4] =
                *(const float4*)(x + (size_t)(t0 + row) * D_IN + kc + c4 * 4);
        }
        __syncthreads();

#pragma unroll
        for (int p = 0; p < 8; p++) {
            int pair = w * 8 + p;
            int t = pair >> 1, k = pair & 1;
            int e = g_idx[(t0 + t) * 2 + k];
            const float4* ap = (const float4*)(A + ((size_t)(e * RANK + r)) * D_IN
                                               + kc + half * 64);
            const float4* xp = (const float4*)(&xs[t][half * 64]);
            float s = 0.f;
#pragma unroll
            for (int i = 0; i < 16; i++) {
                float4 av = ap[i];
                float4 xv = xp[i];
                s += av.x * xv.x + av.y * xv.y + av.z * xv.z + av.w * xv.w;
            }
            acc[p] += s;
        }
        __syncthreads();
    }

#pragma unroll
    for (int p = 0; p < 8; p++) {
        float v = acc[p] + __shfl_xor_sync(0xFFFFFFFFu, acc[p], 1);
        if (half == 0) {
            int pair = w * 8 + p;
            int t = pair >> 1, k = pair & 1;
            g_mid[((size_t)(t0 + t) * 2 + k) * RANK + r] = v;
        }
    }
}

// ---------------------------------------------------------------------------
// Kernel: out[t,o] = bias[o] + sum_k w_k * (B[e_k,o,:] . mid[t,k,:])
// 32 tokens per block: B rows reused across tokens sharing experts (L1/L2).
// thread = (token = tid>>3, o-lane = tid&7); o = j*8 + o-lane, j=0..255.
// ---------------------------------------------------------------------------
__global__ void __launch_bounds__(256)
lora_kernel(const float* __restrict__ B,
            const float* __restrict__ bias,
            float* __restrict__ out) {
    __shared__ float mids_s[32 * 32];
    __shared__ int   eidx_s[64];
    __shared__ float wv_s[64];
    const int t0 = blockIdx.x * 32;
    const int tid = threadIdx.x;

    ((float4*)mids_s)[tid] = ((const float4*)(g_mid + (size_t)t0 * 32))[tid];
    if (tid < 64) {
        eidx_s[tid] = g_idx[t0 * 2 + tid];
        wv_s[tid]   = g_w[t0 * 2 + tid];
    }
    __syncthreads();

    const int tl = tid >> 3;
    const int ol = tid & 7;
    const int t = t0 + tl;
    const float w0 = wv_s[tl * 2 + 0];
    const float w1 = wv_s[tl * 2 + 1];
    const float* B0 = B + (size_t)eidx_s[tl * 2 + 0] * D_OUT * RANK;
    const float* B1 = B + (size_t)eidx_s[tl * 2 + 1] * D_OUT * RANK;

    float m0[RANK], m1[RANK];
#pragma unroll
    for (int q = 0; q < RANK; q++) {
        m0[q] = mids_s[tl * 32 + q];
        m1[q] = mids_s[tl * 32 + 16 + q];
    }

    float* orow = out + (size_t)t * D_OUT;
    for (int j = 0; j < 256; j++) {
        int o = j * 8 + ol;
        const float4* b0 = (const float4*)(B0 + (size_t)o * RANK);
        const float4* b1 = (const float4*)(B1 + (size_t)o * RANK);
        float a0 = 0.f, a1 = 0.f;
#pragma unroll
        for (int q = 0; q < 4; q++) {
            float4 v0 = b0[q];
            float4 v1 = b1[q];
            a0 += v0.x * m0[q * 4 + 0] + v0.y * m0[q * 4 + 1]
                + v0.z * m0[q * 4 + 2] + v0.w * m0[q * 4 + 3];
            a1 += v1.x * m1[q * 4 + 0] + v1.y * m1[q * 4 + 1]
                + v1.z * m1[q * 4 + 2] + v1.w * m1[q * 4 + 3];
        }
        orow[o] = bias[o] + w0 * a0 + w1 * a1;
    }
}

// ---------------------------------------------------------------------------
// bf16 mma.sync GEMM: out[128 x 128 tile] += X . W^T via 3-term hi/lo split.
// 256 threads (8 warps, 2x4 grid, warp tile 64x32), BK=32, 3-stage cp.async.
// Smem per stage: 4 tiles (Xhi,Xlo,Whi,Wlo) x 128 rows x 64B = 32KB.
// Swizzle: 64B rows, chunk' = chunk ^ ((row&3) ^ ((row>>2)&1)) -> conflict-
// free ldmatrix across any 8 consecutive rows.
// ---------------------------------------------------------------------------
#define BM 128
#define BN 128
#define BK 32
#define KITERS (D_IN / BK)          // 64
#define STAGE_BYTES (4 * 128 * 64)  // 32KB
#define GEMM_SMEM (3 * STAGE_BYTES + 1024)
#define TILE_XH 0
#define TILE_XL 8192
#define TILE_WH 16384
#define TILE_WL 24576

__device__ __forceinline__ uint32_t swz_off(int row, int chunk) {
    int s = (row & 3) ^ ((row >> 2) & 1);
    return (uint32_t)(row * 64 + ((chunk ^ s) << 4));
}

__global__ void __launch_bounds__(256)
gemm_mma_kernel(float* __restrict__ out) {
    extern __shared__ char dsm[];
    const uint32_t sbase = (smem_u32(dsm) + 1023) & ~1023u;

    const int tid = threadIdx.x;
    const int wid = tid >> 5;
    const int lane = tid & 31;
    const int bm = blockIdx.y * BM;
    const int bn = blockIdx.x * BN;
    const int wm = (wid & 1) * 64;   // warp row offset
    const int wn = (wid >> 1) * 32;  // warp col offset

    // per-thread load-slot decomposition (8 chunks of 16B per stage)
    // chunk id c = tid + i*256 in [0,2048): tile = c>>9, row=(c>>2)&127, cc=c&3

    // ldmatrix lane addressing
    const int lrA  = (lane & 7) | (((lane >> 3) & 1) << 3);
    const int ksA  = (lane >> 4) & 1;
    const int lrB  = (lane & 7) | (((lane >> 4) & 1) << 3);
    const int ksB  = (lane >> 3) & 1;

    float acc[4][4][4];
#pragma unroll
    for (int i = 0; i < 4; i++)
#pragma unroll
        for (int j = 0; j < 4; j++)
#pragma unroll
            for (int q = 0; q < 4; q++) acc[i][j][q] = 0.f;

#define ISSUE_STAGE(stg, ko_)                                                  \
    do {                                                                       \
        const int kk_ = (ko_) * BK;                                            \
        const uint32_t sb_ = sbase + (stg) * STAGE_BYTES;                      \
        _Pragma("unroll")                                                      \
        for (int i_ = 0; i_ < 8; i_++) {                                       \
            int c_ = tid + i_ * 256;                                           \
            int tile_ = c_ >> 9;                                               \
            int row_ = (c_ >> 2) & 127;                                        \
            int cc_ = c_ & 3;                                                  \
            const __nv_bfloat16* srcb_ =                                       \
                (tile_ == 0) ? g_Xhi : (tile_ == 1) ? g_Xlo                    \
                : (tile_ == 2) ? g_Whi : g_Wlo;                                \
            int grow_ = ((tile_ < 2) ? bm : bn) + row_;                        \
            cp16(sb_ + tile_ * 8192 + swz_off(row_, cc_),                      \
                 srcb_ + (size_t)grow_ * D_IN + kk_ + cc_ * 8);                \
        }                                                                      \
    } while (0)

    ISSUE_STAGE(0, 0);
    asm volatile("cp.async.commit_group;" ::: "memory");
    ISSUE_STAGE(1, 1);
    asm volatile("cp.async.commit_group;" ::: "memory");

    for (int ko = 0; ko < KITERS; ko++) {
        asm volatile("cp.async.wait_group 1;" ::: "memory");
        __syncthreads();

        if (ko + 2 < KITERS) ISSUE_STAGE((ko + 2) % 3, ko + 2);
        asm volatile("cp.async.commit_group;" ::: "memory");

        const uint32_t sb = sbase + (ko % 3) * STAGE_BYTES;
#pragma unroll
        for (int k16 = 0; k16 < BK; k16 += 16) {
            uint32_t axh[4][4], axl[4][4], bwh[2][4], bwl[2][4];
            const int chA = (k16 >> 3) + ksA;
            const int chB = (k16 >> 3) + ksB;
#pragma unroll
            for (int mt = 0; mt < 4; mt++) {
                int row = wm + mt * 16 + lrA;
                uint32_t off = swz_off(row, chA);
                ldsm_x4(axh[mt], sb + TILE_XH + off);
                ldsm_x4(axl[mt], sb + TILE_XL + off);
            }
#pragma unroll
            for (int nt2 = 0; nt2 < 2; nt2++) {
                int row = wn + nt2 * 16 + lrB;
                uint32_t off = swz_off(row, chB);
                ldsm_x4(bwh[nt2], sb + TILE_WH + off);
                ldsm_x4(bwl[nt2], sb + TILE_WL + off);
            }
#pragma unroll
            for (int mt = 0; mt < 4; mt++) {
#pragma unroll
                for (int nt = 0; nt < 4; nt++) {
                    uint32_t* bh = &bwh[nt >> 1][(nt & 1) * 2];
                    uint32_t* bl = &bwl[nt >> 1][(nt & 1) * 2];
                    MMA16816(acc[mt][nt], axh[mt], bh[0], bh[1]);
                    MMA16816(acc[mt][nt], axh[mt], bl[0], bl[1]);
                    MMA16816(acc[mt][nt], axl[mt], bh[0], bh[1]);
                }
            }
        }
    }

    // epilogue: out += acc (out already holds bias + LoRA contribution)
#pragma unroll
    for (int mt = 0; mt < 4; mt++) {
#pragma unroll
        for (int nt = 0; nt < 4; nt++) {
            int row = bm + wm + mt * 16 + (lane >> 2);
            int col = bn + wn + nt * 8 + (lane & 3) * 2;
            float2* p0 = (float2*)(out + (size_t)row * D_OUT + col);
            float2 v0 = *p0;
            v0.x += acc[mt][nt][0];
            v0.y += acc[mt][nt][1];
            *p0 = v0;
            float2* p1 = (float2*)(out + (size_t)(row + 8) * D_OUT + col);
            float2 v1 = *p1;
            v1.x += acc[mt][nt][2];
            v1.y += acc[mt][nt][3];
            *p1 = v1;
        }
    }
#undef ISSUE_STAGE
}

// ---------------------------------------------------------------------------
// Launch
// ---------------------------------------------------------------------------
extern "C" void kernel_launch(void* const* d_in, const int* in_sizes, int n_in,
                              void* d_out, int out_size) {
    const float* x  = (const float*)d_in[0];
    const float* Wm = (const float*)d_in[1];
    const float* bb = (const float*)d_in[2];
    const float* A  = (const float*)d_in[3];
    const float* B  = (const float*)d_in[4];
    const float* gv = (const float*)d_in[5];
    const float* al = (const float*)d_in[6];
    float* out = (float*)d_out;

    int T = in_sizes[0] / D_IN;   // 8192

    static bool init_done = false;
    static __nv_bfloat16 *xh, *xl, *wh, *wl;
    if (!init_done) {
        cudaFuncSetAttribute(gemm_mma_kernel,
                             cudaFuncAttributeMaxDynamicSharedMemorySize,
                             GEMM_SMEM);
        cudaGetSymbolAddress((void**)&xh, g_Xhi);
        cudaGetSymbolAddress((void**)&xl, g_Xlo);
        cudaGetSymbolAddress((void**)&wh, g_Whi);
        cudaGetSymbolAddress((void**)&wl, g_Wlo);
        init_done = true;
    }

    int nx4 = T * D_IN / 4;
    conv_split_kernel<<<(nx4 + 255) / 256, 256>>>(x, xh, xl, nx4);
    int nw4 = D_OUT * D_IN / 4;
    conv_split_kernel<<<(nw4 + 255) / 256, 256>>>(Wm, wh, wl, nw4);

    gnorm_kernel<<<N_EXP, 256>>>(gv);
    route_kernel<<<T, 256>>>(x, gv, al);
    mid_kernel<<<T / 32, 256>>>(x, A);
    lora_kernel<<<T / 32, 256>>>(B, bb, out);   // out = bias + lora contrib
    gemm_mma_kernel<<<dim3(D_OUT / BN, T / BM), 256, GEMM_SMEM>>>(out);
}

// round 4
// speedup vs baseline: 2.3770x; 1.7831x over previous
#include <cuda_runtime.h>
#include <cuda_fp16.h>
#include <math.h>
#include <stdint.h>

// ---------------------------------------------------------------------------
// Shapes (fixed): x [4,2048,2048] -> T=8192, d=2048 ; base_W [2048,2048];
// base_b [2048]; A [16,16,2048]; B [16,2048,16]; gate_v [16,2048];
// alphas[16]; top_k=2
// ---------------------------------------------------------------------------

#define D_IN   2048
#define D_OUT  2048
#define N_EXP  16
#define RANK   16
#define T_MAX  8192
#define EPSV   1e-6f

// Scratch (static device memory -- no allocation)
__device__ float g_gnorm[N_EXP];
__device__ float g_xnorm[T_MAX];
__device__ int   g_idx[T_MAX * 2];
__device__ float g_w[T_MAX * 2];
__device__ float g_midd[(size_t)T_MAX * 256];   // dense mid: [T, E*RANK]

// fp16 operands for tensor-core GEMMs
__device__ __half g_Xh[(size_t)T_MAX * D_IN];
__device__ __half g_Xl[(size_t)T_MAX * D_IN];
__device__ __half g_Wh[(size_t)D_OUT * D_IN];
__device__ __half g_Ah[(size_t)N_EXP * RANK * D_IN];

// ---------------------------------------------------------------------------
// PTX helpers (sm_80-era: cp.async, ldmatrix, mma.sync)
// ---------------------------------------------------------------------------
__device__ __forceinline__ uint32_t smem_u32(const void* p) {
    uint32_t a;
    asm("{ .reg .u64 t; cvta.to.shared.u64 t, %1; cvt.u32.u64 %0, t; }"
        : "=r"(a) : "l"(p));
    return a;
}
__device__ __forceinline__ void cp16(uint32_t dst, const void* src) {
    asm volatile("cp.async.cg.shared.global [%0], [%1], 16;" :: "r"(dst), "l"(src));
}
__device__ __forceinline__ void ldsm_x4(uint32_t* r, uint32_t addr) {
    asm volatile("ldmatrix.sync.aligned.m8n8.x4.shared.b16 {%0,%1,%2,%3}, [%4];"
                 : "=r"(r[0]), "=r"(r[1]), "=r"(r[2]), "=r"(r[3]) : "r"(addr));
}
#define MMA16816(cd, af, b0, b1)                                              \
    asm volatile("mma.sync.aligned.m16n8k16.row.col.f32.f16.f16.f32 "        \
                 "{%0,%1,%2,%3}, {%4,%5,%6,%7}, {%8,%9}, {%0,%1,%2,%3};"      \
                 : "+f"((cd)[0]), "+f"((cd)[1]), "+f"((cd)[2]), "+f"((cd)[3]) \
                 : "r"((af)[0]), "r"((af)[1]), "r"((af)[2]), "r"((af)[3]),    \
                   "r"(b0), "r"(b1))

// ---------------------------------------------------------------------------
// Kernel: X fp32 -> (hi,lo) fp16 split + per-token norm. One block per token.
// ---------------------------------------------------------------------------
__global__ void __launch_bounds__(256)
convx_kernel(const float* __restrict__ x) {
    const int t = blockIdx.x;
    const int tid = threadIdx.x;
    const float4* xr = (const float4*)(x + (size_t)t * D_IN);
    __half2* hp = (__half2*)(g_Xh + (size_t)t * D_IN);
    __half2* lp = (__half2*)(g_Xl + (size_t)t * D_IN);

    float xx = 0.f;
#pragma unroll
    for (int i = 0; i < 2; i++) {
        int j = tid + i * 256;             // float4 index in [0,512)
        float4 v = xr[j];
        xx += v.x * v.x + v.y * v.y + v.z * v.z + v.w * v.w;
        __half hx = __float2half(v.x);
        __half hy = __float2half(v.y);
        __half hz = __float2half(v.z);
        __half hw = __float2half(v.w);
        hp[j * 2 + 0] = __half2(hx, hy);
        hp[j * 2 + 1] = __half2(hz, hw);
        lp[j * 2 + 0] = __half2(__float2half(v.x - __half2float(hx)),
                                __float2half(v.y - __half2float(hy)));
        lp[j * 2 + 1] = __half2(__float2half(v.z - __half2float(hz)),
                                __float2half(v.w - __half2float(hw)));
    }
    // block reduce xx
    __shared__ float red[256];
    red[tid] = xx;
    __syncthreads();
    for (int st = 128; st > 0; st >>= 1) {
        if (tid < st) red[tid] += red[tid + st];
        __syncthreads();
    }
    if (tid == 0) g_xnorm[t] = sqrtf(red[0]) + EPSV;
}

// ---------------------------------------------------------------------------
// Kernel: generic fp32 -> fp16 conversion
// ---------------------------------------------------------------------------
__global__ void convh_kernel(const float* __restrict__ src,
                             __half* __restrict__ dst, int n4) {
    int i = blockIdx.x * blockDim.x + threadIdx.x;
    if (i >= n4) return;
    float4 v = ((const float4*)src)[i];
    __half2* dp = (__half2*)dst;
    dp[2 * i + 0] = __half2(__float2half(v.x), __float2half(v.y));
    dp[2 * i + 1] = __half2(__float2half(v.z), __float2half(v.w));
}

// ---------------------------------------------------------------------------
// Kernel: gate vector norms
// ---------------------------------------------------------------------------
__global__ void gnorm_kernel(const float* __restrict__ gv) {
    int e = blockIdx.x;
    float s = 0.f;
    for (int j = threadIdx.x; j < D_IN; j += 256) {
        float v = gv[e * D_IN + j];
        s += v * v;
    }
    __shared__ float red[256];
    red[threadIdx.x] = s;
    __syncthreads();
    for (int st = 128; st > 0; st >>= 1) {
        if (threadIdx.x < st) red[threadIdx.x] += red[threadIdx.x + st];
        __syncthreads();
    }
    if (threadIdx.x == 0) g_gnorm[e] = sqrtf(red[0]) + EPSV;
}

// ---------------------------------------------------------------------------
// Kernel: routing (float4, top-2 + softmax, fold alpha/r). One block/token.
// ---------------------------------------------------------------------------
__global__ void __launch_bounds__(256)
route_kernel(const float* __restrict__ x,
             const float* __restrict__ gv,
             const float* __restrict__ alphas) {
    const int t = blockIdx.x;
    const float4* xr = (const float4*)(x + (size_t)t * D_IN);
    const float4* gv4 = (const float4*)gv;

    float s[N_EXP];
#pragma unroll
    for (int e = 0; e < N_EXP; e++) s[e] = 0.f;

#pragma unroll
    for (int i = 0; i < 2; i++) {
        int j = threadIdx.x + i * 256;
        float4 xv = xr[j];
#pragma unroll
        for (int e = 0; e < N_EXP; e++) {
            float4 g = gv4[e * 512 + j];
            s[e] += xv.x * g.x + xv.y * g.y + xv.z * g.z + xv.w * g.w;
        }
    }
#pragma unroll
    for (int off = 16; off > 0; off >>= 1)
#pragma unroll
        for (int e = 0; e < N_EXP; e++)
            s[e] += __shfl_down_sync(0xFFFFFFFFu, s[e], off);

    __shared__ float sm[8][N_EXP];
    int w = threadIdx.x >> 5, l = threadIdx.x & 31;
    if (l == 0) {
#pragma unroll
        for (int e = 0; e < N_EXP; e++) sm[w][e] = s[e];
    }
    __syncthreads();
    if (threadIdx.x == 0) {
        float fs[N_EXP];
#pragma unroll
        for (int e = 0; e < N_EXP; e++) fs[e] = 0.f;
        for (int ww = 0; ww < 8; ww++)
#pragma unroll
            for (int e = 0; e < N_EXP; e++) fs[e] += sm[ww][e];

        float inv = 1.f / (g_xnorm[t] * sqrtf((float)D_IN));
        float sc[N_EXP];
#pragma unroll
        for (int e = 0; e < N_EXP; e++) sc[e] = fs[e] * inv / g_gnorm[e];

        int i0 = 0;
#pragma unroll
        for (int e = 1; e < N_EXP; e++) if (sc[e] > sc[i0]) i0 = e;
        int i1 = (i0 == 0) ? 1 : 0;
#pragma unroll
        for (int e = 0; e < N_EXP; e++)
            if (e != i0 && sc[e] > sc[i1]) i1 = e;

        float e1 = expf(sc[i1] - sc[i0]);
        float denom = 1.f + e1;
        g_idx[t * 2 + 0] = i0;
        g_idx[t * 2 + 1] = i1;
        g_w[t * 2 + 0] = (1.f / denom) * alphas[i0] * (1.f / (float)RANK);
        g_w[t * 2 + 1] = (e1 / denom) * alphas[i1] * (1.f / (float)RANK);
    }
}

// ---------------------------------------------------------------------------
// Kernel: out[t,o] = bias[o] + sum_k w_k * (B[e_k,o,:] . midd[t, e_k*16 + :])
// 32 tokens per block; thread = (token = tid>>3, o-lane = tid&7).
// ---------------------------------------------------------------------------
__global__ void __launch_bounds__(256)
lora_kernel(const float* __restrict__ B,
            const float* __restrict__ bias,
            float* __restrict__ out) {
    const int t0 = blockIdx.x * 32;
    const int tid = threadIdx.x;
    const int tl = tid >> 3;
    const int ol = tid & 7;
    const int t = t0 + tl;

    const int e0 = g_idx[t * 2 + 0];
    const int e1 = g_idx[t * 2 + 1];
    const float w0 = g_w[t * 2 + 0];
    const float w1 = g_w[t * 2 + 1];
    const float* B0 = B + (size_t)e0 * D_OUT * RANK;
    const float* B1 = B + (size_t)e1 * D_OUT * RANK;

    float m0[RANK], m1[RANK];
    const float4* mp0 = (const float4*)(g_midd + (size_t)t * 256 + e0 * RANK);
    const float4* mp1 = (const float4*)(g_midd + (size_t)t * 256 + e1 * RANK);
#pragma unroll
    for (int q = 0; q < 4; q++) {
        ((float4*)m0)[q] = mp0[q];
        ((float4*)m1)[q] = mp1[q];
    }

    float* orow = out + (size_t)t * D_OUT;
    for (int j = 0; j < 256; j++) {
        int o = j * 8 + ol;
        const float4* b0 = (const float4*)(B0 + (size_t)o * RANK);
        const float4* b1 = (const float4*)(B1 + (size_t)o * RANK);
        float a0 = 0.f, a1 = 0.f;
#pragma unroll
        for (int q = 0; q < 4; q++) {
            float4 v0 = b0[q];
            float4 v1 = b1[q];
            a0 += v0.x * m0[q * 4 + 0] + v0.y * m0[q * 4 + 1]
                + v0.z * m0[q * 4 + 2] + v0.w * m0[q * 4 + 3];
            a1 += v1.x * m1[q * 4 + 0] + v1.y * m1[q * 4 + 1]
                + v1.z * m1[q * 4 + 2] + v1.w * m1[q * 4 + 3];
        }
        orow[o] = bias[o] + w0 * a0 + w1 * a1;
    }
}

// ---------------------------------------------------------------------------
// fp16 mma.sync GEMM: out[128 x 128 tile] (+)= X . Wop^T, 2-term X split.
// 256 threads (8 warps, 2x4, warp tile 64x32), BK=32, 3-stage cp.async,
// 3 smem tiles per stage (Xh, Xl, Wh) = 24KB -> 2 CTAs/SM.
// ---------------------------------------------------------------------------
#define BM 128
#define BN 128
#define BK 32
#define KITERS (D_IN / BK)          // 64
#define STAGE_BYTES (3 * 128 * 64)  // 24KB
#define GEMM_SMEM (3 * STAGE_BYTES + 1024)
#define TILE_XH 0
#define TILE_XL 8192
#define TILE_WH 16384

__device__ __forceinline__ uint32_t swz_off(int row, int chunk) {
    int s = (row & 3) ^ ((row >> 2) & 1);
    return (uint32_t)(row * 64 + ((chunk ^ s) << 4));
}

__global__ void __launch_bounds__(256, 2)
gemm_mma_kernel(const __half* __restrict__ Wop,
                float* __restrict__ out, int ldout, int accum) {
    extern __shared__ char dsm[];
    const uint32_t sbase = (smem_u32(dsm) + 1023) & ~1023u;

    const int tid = threadIdx.x;
    const int wid = tid >> 5;
    const int lane = tid & 31;
    const int bm = blockIdx.y * BM;
    const int bn = blockIdx.x * BN;
    const int wm = (wid & 1) * 64;
    const int wn = (wid >> 1) * 32;

    const int lrA = (lane & 7) | (((lane >> 3) & 1) << 3);
    const int ksA = (lane >> 4) & 1;
    const int lrB = (lane & 7) | (((lane >> 4) & 1) << 3);
    const int ksB = (lane >> 3) & 1;

    float acc[4][4][4];
#pragma unroll
    for (int i = 0; i < 4; i++)
#pragma unroll
        for (int j = 0; j < 4; j++)
#pragma unroll
            for (int q = 0; q < 4; q++) acc[i][j][q] = 0.f;

#define ISSUE_STAGE(stg, ko_)                                                  \
    do {                                                                       \
        const int kk_ = (ko_) * BK;                                            \
        const uint32_t sb_ = sbase + (stg) * STAGE_BYTES;                      \
        _Pragma("unroll")                                                      \
        for (int i_ = 0; i_ < 6; i_++) {                                       \
            int c_ = tid + i_ * 256;   /* [0,1536) */                          \
            int tile_ = c_ >> 9;                                               \
            int row_ = (c_ >> 2) & 127;                                        \
            int cc_ = c_ & 3;                                                  \
            const __half* srcb_ =                                              \
                (tile_ == 0) ? g_Xh : (tile_ == 1) ? g_Xl : Wop;               \
            int grow_ = ((tile_ < 2) ? bm : bn) + row_;                        \
            cp16(sb_ + tile_ * 8192 + swz_off(row_, cc_),                      \
                 srcb_ + (size_t)grow_ * D_IN + kk_ + cc_ * 8);                \
        }                                                                      \
    } while (0)

    ISSUE_STAGE(0, 0);
    asm volatile("cp.async.commit_group;" ::: "memory");
    ISSUE_STAGE(1, 1);
    asm volatile("cp.async.commit_group;" ::: "memory");

    for (int ko = 0; ko < KITERS; ko++) {
        asm volatile("cp.async.wait_group 1;" ::: "memory");
        __syncthreads();

        if (ko + 2 < KITERS) ISSUE_STAGE((ko + 2) % 3, ko + 2);
        asm volatile("cp.async.commit_group;" ::: "memory");

        const uint32_t sb = sbase + (ko % 3) * STAGE_BYTES;
#pragma unroll
        for (int k16 = 0; k16 < BK; k16 += 16) {
            uint32_t axh[4][4], axl[4][4], bwh[2][4];
            const int chA = (k16 >> 3) + ksA;
            const int chB = (k16 >> 3) + ksB;
#pragma unroll
            for (int mt = 0; mt < 4; mt++) {
                int row = wm + mt * 16 + lrA;
                uint32_t off = swz_off(row, chA);
                ldsm_x4(axh[mt], sb + TILE_XH + off);
                ldsm_x4(axl[mt], sb + TILE_XL + off);
            }
#pragma unroll
            for (int nt2 = 0; nt2 < 2; nt2++) {
                int row = wn + nt2 * 16 + lrB;
                ldsm_x4(bwh[nt2], sb + TILE_WH + swz_off(row, chB));
            }
#pragma unroll
            for (int mt = 0; mt < 4; mt++) {
#pragma unroll
                for (int nt = 0; nt < 4; nt++) {
                    uint32_t* bh = &bwh[nt >> 1][(nt & 1) * 2];
                    MMA16816(acc[mt][nt], axh[mt], bh[0], bh[1]);
                    MMA16816(acc[mt][nt], axl[mt], bh[0], bh[1]);
                }
            }
        }
    }

    // epilogue
#pragma unroll
    for (int mt = 0; mt < 4; mt++) {
#pragma unroll
        for (int nt = 0; nt < 4; nt++) {
            int row = bm + wm + mt * 16 + (lane >> 2);
            int col = bn + wn + nt * 8 + (lane & 3) * 2;
            float2* p0 = (float2*)(out + (size_t)row * ldout + col);
            float2* p1 = (float2*)(out + (size_t)(row + 8) * ldout + col);
            if (accum) {
                float2 v0 = *p0;
                v0.x += acc[mt][nt][0];
                v0.y += acc[mt][nt][1];
                *p0 = v0;
                float2 v1 = *p1;
                v1.x += acc[mt][nt][2];
                v1.y += acc[mt][nt][3];
                *p1 = v1;
            } else {
                *p0 = make_float2(acc[mt][nt][0], acc[mt][nt][1]);
                *p1 = make_float2(acc[mt][nt][2], acc[mt][nt][3]);
            }
        }
    }
#undef ISSUE_STAGE
}

// ---------------------------------------------------------------------------
// Launch
// ---------------------------------------------------------------------------
extern "C" void kernel_launch(void* const* d_in, const int* in_sizes, int n_in,
                              void* d_out, int out_size) {
    const float* x  = (const float*)d_in[0];
    const float* Wm = (const float*)d_in[1];
    const float* bb = (const float*)d_in[2];
    const float* A  = (const float*)d_in[3];
    const float* B  = (const float*)d_in[4];
    const float* gv = (const float*)d_in[5];
    const float* al = (const float*)d_in[6];
    float* out = (float*)d_out;

    int T = in_sizes[0] / D_IN;   // 8192

    static bool init_done = false;
    static __half *wh, *ah;
    static float* midd;
    if (!init_done) {
        cudaFuncSetAttribute(gemm_mma_kernel,
                             cudaFuncAttributeMaxDynamicSharedMemorySize,
                             GEMM_SMEM);
        cudaGetSymbolAddress((void**)&wh, g_Wh);
        cudaGetSymbolAddress((void**)&ah, g_Ah);
        cudaGetSymbolAddress((void**)&midd, g_midd);
        init_done = true;
    }

    convx_kernel<<<T, 256>>>(x);                                   // Xh/Xl + xnorm
    convh_kernel<<<(D_OUT * D_IN / 4 + 255) / 256, 256>>>(Wm, wh, D_OUT * D_IN / 4);
    convh_kernel<<<(N_EXP * RANK * D_IN / 4 + 255) / 256, 256>>>(A, ah, N_EXP * RANK * D_IN / 4);
    gnorm_kernel<<<N_EXP, 256>>>(gv);
    route_kernel<<<T, 256>>>(x, gv, al);

    // dense mid = X @ A^T  -> g_midd [T, 256]
    gemm_mma_kernel<<<dim3(256 / BN, T / BM), 256, GEMM_SMEM>>>(ah, midd, 256, 0);
    // out = bias + weighted LoRA contribution
    lora_kernel<<<T / 32, 256>>>(B, bb, out);
    // out += X @ W^T
    gemm_mma_kernel<<<dim3(D_OUT / BN, T / BM), 256, GEMM_SMEM>>>(wh, out, D_OUT, 1);
}

// round 5
// speedup vs baseline: 3.1607x; 1.3297x over previous
#include <cuda_runtime.h>
#include <cuda_fp16.h>
#include <math.h>
#include <stdint.h>

// ---------------------------------------------------------------------------
// Shapes (fixed): x [4,2048,2048] -> T=8192, d=2048 ; base_W [2048,2048];
// base_b [2048]; A [16,16,2048]; B [16,2048,16]; gate_v [16,2048];
// alphas[16]; top_k=2
// ---------------------------------------------------------------------------

#define D_IN   2048
#define D_OUT  2048
#define N_EXP  16
#define RANK   16
#define T_MAX  8192
#define EPSV   1e-6f
#define N_WA   (D_OUT + N_EXP * RANK)   // 2304 rows: W then A

// Scratch (static device memory -- no allocation)
__device__ float g_gnorm[N_EXP];
__device__ float g_xnorm[T_MAX];
__device__ int   g_idx[T_MAX * 2];
__device__ float g_w[T_MAX * 2];
__device__ float g_midd[(size_t)T_MAX * 256];   // dense mid: [T, E*RANK]

// fp16 operands
__device__ __half g_Xh[(size_t)T_MAX * D_IN];
__device__ __half g_WA[(size_t)N_WA * D_IN];    // rows 0..2047: W, 2048..2303: A

// ---------------------------------------------------------------------------
// PTX helpers (sm_80-era: cp.async, ldmatrix, mma.sync)
// ---------------------------------------------------------------------------
__device__ __forceinline__ uint32_t smem_u32(const void* p) {
    uint32_t a;
    asm("{ .reg .u64 t; cvta.to.shared.u64 t, %1; cvt.u32.u64 %0, t; }"
        : "=r"(a) : "l"(p));
    return a;
}
__device__ __forceinline__ void cp16(uint32_t dst, const void* src) {
    asm volatile("cp.async.cg.shared.global [%0], [%1], 16;" :: "r"(dst), "l"(src));
}
__device__ __forceinline__ void ldsm_x4(uint32_t* r, uint32_t addr) {
    asm volatile("ldmatrix.sync.aligned.m8n8.x4.shared.b16 {%0,%1,%2,%3}, [%4];"
                 : "=r"(r[0]), "=r"(r[1]), "=r"(r[2]), "=r"(r[3]) : "r"(addr));
}
#define MMA16816(cd, af, b0, b1)                                              \
    asm volatile("mma.sync.aligned.m16n8k16.row.col.f32.f16.f16.f32 "        \
                 "{%0,%1,%2,%3}, {%4,%5,%6,%7}, {%8,%9}, {%0,%1,%2,%3};"      \
                 : "+f"((cd)[0]), "+f"((cd)[1]), "+f"((cd)[2]), "+f"((cd)[3]) \
                 : "r"((af)[0]), "r"((af)[1]), "r"((af)[2]), "r"((af)[3]),    \
                   "r"(b0), "r"(b1))

// ---------------------------------------------------------------------------
// Kernel: X fp32 -> fp16 + per-token norm. One block per token.
// ---------------------------------------------------------------------------
__global__ void __launch_bounds__(256)
convx_kernel(const float* __restrict__ x) {
    const int t = blockIdx.x;
    const int tid = threadIdx.x;
    const float4* xr = (const float4*)(x + (size_t)t * D_IN);
    __half2* hp = (__half2*)(g_Xh + (size_t)t * D_IN);

    float xx = 0.f;
#pragma unroll
    for (int i = 0; i < 2; i++) {
        int j = tid + i * 256;             // float4 index in [0,512)
        float4 v = xr[j];
        xx += v.x * v.x + v.y * v.y + v.z * v.z + v.w * v.w;
        hp[j * 2 + 0] = __half2(__float2half(v.x), __float2half(v.y));
        hp[j * 2 + 1] = __half2(__float2half(v.z), __float2half(v.w));
    }
    __shared__ float red[256];
    red[tid] = xx;
    __syncthreads();
    for (int st = 128; st > 0; st >>= 1) {
        if (tid < st) red[tid] += red[tid + st];
        __syncthreads();
    }
    if (tid == 0) g_xnorm[t] = sqrtf(red[0]) + EPSV;
}

// ---------------------------------------------------------------------------
// Kernel: generic fp32 -> fp16 conversion
// ---------------------------------------------------------------------------
__global__ void convh_kernel(const float* __restrict__ src,
                             __half* __restrict__ dst, int n4) {
    int i = blockIdx.x * blockDim.x + threadIdx.x;
    if (i >= n4) return;
    float4 v = ((const float4*)src)[i];
    __half2* dp = (__half2*)dst;
    dp[2 * i + 0] = __half2(__float2half(v.x), __float2half(v.y));
    dp[2 * i + 1] = __half2(__float2half(v.z), __float2half(v.w));
}

// ---------------------------------------------------------------------------
// Kernel: gate vector norms
// ---------------------------------------------------------------------------
__global__ void gnorm_kernel(const float* __restrict__ gv) {
    int e = blockIdx.x;
    float s = 0.f;
    for (int j = threadIdx.x; j < D_IN; j += 256) {
        float v = gv[e * D_IN + j];
        s += v * v;
    }
    __shared__ float red[256];
    red[threadIdx.x] = s;
    __syncthreads();
    for (int st = 128; st > 0; st >>= 1) {
        if (threadIdx.x < st) red[threadIdx.x] += red[threadIdx.x + st];
        __syncthreads();
    }
    if (threadIdx.x == 0) g_gnorm[e] = sqrtf(red[0]) + EPSV;
}

// ---------------------------------------------------------------------------
// Kernel: routing (float4, top-2 + softmax, fold alpha/r). One block/token.
// ---------------------------------------------------------------------------
__global__ void __launch_bounds__(256)
route_kernel(const float* __restrict__ x,
             const float* __restrict__ gv,
             const float* __restrict__ alphas) {
    const int t = blockIdx.x;
    const float4* xr = (const float4*)(x + (size_t)t * D_IN);
    const float4* gv4 = (const float4*)gv;

    float s[N_EXP];
#pragma unroll
    for (int e = 0; e < N_EXP; e++) s[e] = 0.f;

#pragma unroll
    for (int i = 0; i < 2; i++) {
        int j = threadIdx.x + i * 256;
        float4 xv = xr[j];
#pragma unroll
        for (int e = 0; e < N_EXP; e++) {
            float4 g = gv4[e * 512 + j];
            s[e] += xv.x * g.x + xv.y * g.y + xv.z * g.z + xv.w * g.w;
        }
    }
#pragma unroll
    for (int off = 16; off > 0; off >>= 1)
#pragma unroll
        for (int e = 0; e < N_EXP; e++)
            s[e] += __shfl_down_sync(0xFFFFFFFFu, s[e], off);

    __shared__ float sm[8][N_EXP];
    int w = threadIdx.x >> 5, l = threadIdx.x & 31;
    if (l == 0) {
#pragma unroll
        for (int e = 0; e < N_EXP; e++) sm[w][e] = s[e];
    }
    __syncthreads();
    if (threadIdx.x == 0) {
        float fs[N_EXP];
#pragma unroll
        for (int e = 0; e < N_EXP; e++) fs[e] = 0.f;
        for (int ww = 0; ww < 8; ww++)
#pragma unroll
            for (int e = 0; e < N_EXP; e++) fs[e] += sm[ww][e];

        float inv = 1.f / (g_xnorm[t] * sqrtf((float)D_IN));
        float sc[N_EXP];
#pragma unroll
        for (int e = 0; e < N_EXP; e++) sc[e] = fs[e] * inv / g_gnorm[e];

        int i0 = 0;
#pragma unroll
        for (int e = 1; e < N_EXP; e++) if (sc[e] > sc[i0]) i0 = e;
        int i1 = (i0 == 0) ? 1 : 0;
#pragma unroll
        for (int e = 0; e < N_EXP; e++)
            if (e != i0 && sc[e] > sc[i1]) i1 = e;

        float e1 = expf(sc[i1] - sc[i0]);
        float denom = 1.f + e1;
        g_idx[t * 2 + 0] = i0;
        g_idx[t * 2 + 1] = i1;
        g_w[t * 2 + 0] = (1.f / denom) * alphas[i0] * (1.f / (float)RANK);
        g_w[t * 2 + 1] = (e1 / denom) * alphas[i1] * (1.f / (float)RANK);
    }
}

// ---------------------------------------------------------------------------
// Kernel: out[t,o] += bias[o] + sum_k w_k * (B[e_k,o,:] . midd[t, e_k*16+:])
// (out already holds X @ W^T from the fused GEMM)
// 32 tokens per block; thread = (token = tid>>3, o-lane = tid&7).
// ---------------------------------------------------------------------------
__global__ void __launch_bounds__(256)
lora_kernel(const float* __restrict__ B,
            const float* __restrict__ bias,
            float* __restrict__ out) {
    const int t0 = blockIdx.x * 32;
    const int tid = threadIdx.x;
    const int tl = tid >> 3;
    const int ol = tid & 7;
    const int t = t0 + tl;

    const int e0 = g_idx[t * 2 + 0];
    const int e1 = g_idx[t * 2 + 1];
    const float w0 = g_w[t * 2 + 0];
    const float w1 = g_w[t * 2 + 1];
    const float* B0 = B + (size_t)e0 * D_OUT * RANK;
    const float* B1 = B + (size_t)e1 * D_OUT * RANK;

    float m0[RANK], m1[RANK];
    const float4* mp0 = (const float4*)(g_midd + (size_t)t * 256 + e0 * RANK);
    const float4* mp1 = (const float4*)(g_midd + (size_t)t * 256 + e1 * RANK);
#pragma unroll
    for (int q = 0; q < 4; q++) {
        ((float4*)m0)[q] = mp0[q];
        ((float4*)m1)[q] = mp1[q];
    }

    float* orow = out + (size_t)t * D_OUT;
    for (int j = 0; j < 256; j++) {
        int o = j * 8 + ol;
        const float4* b0 = (const float4*)(B0 + (size_t)o * RANK);
        const float4* b1 = (const float4*)(B1 + (size_t)o * RANK);
        float a0 = 0.f, a1 = 0.f;
#pragma unroll
        for (int q = 0; q < 4; q++) {
            float4 v0 = b0[q];
            float4 v1 = b1[q];
            a0 += v0.x * m0[q * 4 + 0] + v0.y * m0[q * 4 + 1]
                + v0.z * m0[q * 4 + 2] + v0.w * m0[q * 4 + 3];
            a1 += v1.x * m1[q * 4 + 0] + v1.y * m1[q * 4 + 1]
                + v1.z * m1[q * 4 + 2] + v1.w * m1[q * 4 + 3];
        }
        orow[o] += bias[o] + w0 * a0 + w1 * a1;
    }
}

// ---------------------------------------------------------------------------
// Fused fp16 mma.sync GEMM over WA = [W ; A]:
//   col-blocks 0..15 -> out  = X @ W^T   (overwrite, ld=2048)
//   col-blocks 16,17 -> midd = X @ A^T   (overwrite, ld=256)
// 256 threads (8 warps, 2x4, warp tile 64x32), BK=32, 3-stage cp.async,
// 2 smem tiles/stage (Xh, WA) = 16KB -> 48KB total, 2 CTAs/SM.
// ---------------------------------------------------------------------------
#define BM 128
#define BN 128
#define BK 32
#define KITERS (D_IN / BK)          // 64
#define STAGE_BYTES (2 * 128 * 64)  // 16KB
#define GEMM_SMEM (3 * STAGE_BYTES + 1024)
#define TILE_XH 0
#define TILE_WA 8192

__device__ __forceinline__ uint32_t swz_off(int row, int chunk) {
    int s = (row & 3) ^ ((row >> 2) & 1);
    return (uint32_t)(row * 64 + ((chunk ^ s) << 4));
}

__global__ void __launch_bounds__(256, 2)
gemm_fused_kernel(float* __restrict__ out, float* __restrict__ midd) {
    extern __shared__ char dsm[];
    const uint32_t sbase = (smem_u32(dsm) + 1023) & ~1023u;

    const int tid = threadIdx.x;
    const int wid = tid >> 5;
    const int lane = tid & 31;
    const int bm = blockIdx.y * BM;
    const int bnr = blockIdx.x * BN;      // row base into WA
    const int wm = (wid & 1) * 64;
    const int wn = (wid >> 1) * 32;

    const int lrA = (lane & 7) | (((lane >> 3) & 1) << 3);
    const int ksA = (lane >> 4) & 1;
    const int lrB = (lane & 7) | (((lane >> 4) & 1) << 3);
    const int ksB = (lane >> 3) & 1;

    float acc[4][4][4];
#pragma unroll
    for (int i = 0; i < 4; i++)
#pragma unroll
        for (int j = 0; j < 4; j++)
#pragma unroll
            for (int q = 0; q < 4; q++) acc[i][j][q] = 0.f;

#define ISSUE_STAGE(stg, ko_)                                                  \
    do {                                                                       \
        const int kk_ = (ko_) * BK;                                            \
        const uint32_t sb_ = sbase + (stg) * STAGE_BYTES;                      \
        _Pragma("unroll")                                                      \
        for (int i_ = 0; i_ < 4; i_++) {                                       \
            int c_ = tid + i_ * 256;   /* [0,1024) */                          \
            int tile_ = c_ >> 9;                                               \
            int row_ = (c_ >> 2) & 127;                                        \
            int cc_ = c_ & 3;                                                  \
            const __half* srcb_ = (tile_ == 0) ? (g_Xh + (size_t)(bm + row_) * D_IN) \
                                               : (g_WA + (size_t)(bnr + row_) * D_IN); \
            cp16(sb_ + tile_ * 8192 + swz_off(row_, cc_),                      \
                 srcb_ + kk_ + cc_ * 8);                                       \
        }                                                                      \
    } while (0)

    ISSUE_STAGE(0, 0);
    asm volatile("cp.async.commit_group;" ::: "memory");
    ISSUE_STAGE(1, 1);
    asm volatile("cp.async.commit_group;" ::: "memory");

    for (int ko = 0; ko < KITERS; ko++) {
        asm volatile("cp.async.wait_group 1;" ::: "memory");
        __syncthreads();

        if (ko + 2 < KITERS) ISSUE_STAGE((ko + 2) % 3, ko + 2);
        asm volatile("cp.async.commit_group;" ::: "memory");

        const uint32_t sb = sbase + (ko % 3) * STAGE_BYTES;
#pragma unroll
        for (int k16 = 0; k16 < BK; k16 += 16) {
            uint32_t axh[4][4], bwh[2][4];
            const int chA = (k16 >> 3) + ksA;
            const int chB = (k16 >> 3) + ksB;
#pragma unroll
            for (int mt = 0; mt < 4; mt++) {
                int row = wm + mt * 16 + lrA;
                ldsm_x4(axh[mt], sb + TILE_XH + swz_off(row, chA));
            }
#pragma unroll
            for (int nt2 = 0; nt2 < 2; nt2++) {
                int row = wn + nt2 * 16 + lrB;
                ldsm_x4(bwh[nt2], sb + TILE_WA + swz_off(row, chB));
            }
#pragma unroll
            for (int mt = 0; mt < 4; mt++) {
#pragma unroll
                for (int nt = 0; nt < 4; nt++) {
                    uint32_t* bh = &bwh[nt >> 1][(nt & 1) * 2];
                    MMA16816(acc[mt][nt], axh[mt], bh[0], bh[1]);
                }
            }
        }
    }

    // epilogue: route to out or midd (overwrite both)
    float* dst;
    int ld, colbase;
    if (blockIdx.x < 16) {
        dst = out; ld = D_OUT; colbase = blockIdx.x * BN;
    } else {
        dst = midd; ld = 256; colbase = (blockIdx.x - 16) * BN;
    }
#pragma unroll
    for (int mt = 0; mt < 4; mt++) {
#pragma unroll
        for (int nt = 0; nt < 4; nt++) {
            int row = bm + wm + mt * 16 + (lane >> 2);
            int col = colbase + wn + nt * 8 + (lane & 3) * 2;
            *(float2*)(dst + (size_t)row * ld + col) =
                make_float2(acc[mt][nt][0], acc[mt][nt][1]);
            *(float2*)(dst + (size_t)(row + 8) * ld + col) =
                make_float2(acc[mt][nt][2], acc[mt][nt][3]);
        }
    }
#undef ISSUE_STAGE
}

// ---------------------------------------------------------------------------
// Launch
// ---------------------------------------------------------------------------
extern "C" void kernel_launch(void* const* d_in, const int* in_sizes, int n_in,
                              void* d_out, int out_size) {
    const float* x  = (const float*)d_in[0];
    const float* Wm = (const float*)d_in[1];
    const float* bb = (const float*)d_in[2];
    const float* A  = (const float*)d_in[3];
    const float* B  = (const float*)d_in[4];
    const float* gv = (const float*)d_in[5];
    const float* al = (const float*)d_in[6];
    float* out = (float*)d_out;

    int T = in_sizes[0] / D_IN;   // 8192

    static bool init_done = false;
    static __half* wa;
    static float* midd;
    if (!init_done) {
        cudaFuncSetAttribute(gemm_fused_kernel,
                             cudaFuncAttributeMaxDynamicSharedMemorySize,
                             GEMM_SMEM);
        cudaGetSymbolAddress((void**)&wa, g_WA);
        cudaGetSymbolAddress((void**)&midd, g_midd);
        init_done = true;
    }

    convx_kernel<<<T, 256>>>(x);                       // Xh + xnorm
    convh_kernel<<<(D_OUT * D_IN / 4 + 255) / 256, 256>>>(Wm, wa, D_OUT * D_IN / 4);
    convh_kernel<<<(N_EXP * RANK * D_IN / 4 + 255) / 256, 256>>>(
        A, wa + (size_t)D_OUT * D_IN, N_EXP * RANK * D_IN / 4);
    gnorm_kernel<<<N_EXP, 256>>>(gv);
    route_kernel<<<T, 256>>>(x, gv, al);

    // fused: out = X @ W^T ; midd = X @ A^T
    gemm_fused_kernel<<<dim3(N_WA / BN, T / BM), 256, GEMM_SMEM>>>(out, midd);
    // out += bias + weighted LoRA contribution
    lora_kernel<<<T / 32, 256>>>(B, bb, out);
}

// round 6
// speedup vs baseline: 3.4772x; 1.1001x over previous
#include <cuda_runtime.h>
#include <cuda_fp16.h>
#include <math.h>
#include <stdint.h>

// ---------------------------------------------------------------------------
// Shapes (fixed): x [4,2048,2048] -> T=8192, d=2048 ; base_W [2048,2048];
// base_b [2048]; A [16,16,2048]; B [16,2048,16]; gate_v [16,2048];
// alphas[16]; top_k=2
// ---------------------------------------------------------------------------

#define D_IN   2048
#define D_OUT  2048
#define N_EXP  16
#define RANK   16
#define T_MAX  8192
#define EPSV   1e-6f
#define N_WA   (D_OUT + N_EXP * RANK)   // 2304 rows: W then A

// Scratch (static device memory -- no allocation)
__device__ float g_gnorm[N_EXP];
__device__ float g_xnorm[T_MAX];
__device__ float g_dots[T_MAX * N_EXP];         // raw x.gv dots
__device__ int   g_idx[T_MAX * 2];
__device__ float g_w[T_MAX * 2];
__device__ float g_midd[(size_t)T_MAX * 256];   // dense mid: [T, E*RANK]

// fp16 operands
__device__ __half g_Xh[(size_t)T_MAX * D_IN];
__device__ __half g_WA[(size_t)N_WA * D_IN];    // rows 0..2047: W, 2048..2303: A

// ---------------------------------------------------------------------------
// PTX helpers (sm_80-era: cp.async, ldmatrix, mma.sync)
// ---------------------------------------------------------------------------
__device__ __forceinline__ uint32_t smem_u32(const void* p) {
    uint32_t a;
    asm("{ .reg .u64 t; cvta.to.shared.u64 t, %1; cvt.u32.u64 %0, t; }"
        : "=r"(a) : "l"(p));
    return a;
}
__device__ __forceinline__ void cp16(uint32_t dst, const void* src) {
    asm volatile("cp.async.cg.shared.global [%0], [%1], 16;" :: "r"(dst), "l"(src));
}
__device__ __forceinline__ void ldsm_x4(uint32_t* r, uint32_t addr) {
    asm volatile("ldmatrix.sync.aligned.m8n8.x4.shared.b16 {%0,%1,%2,%3}, [%4];"
                 : "=r"(r[0]), "=r"(r[1]), "=r"(r[2]), "=r"(r[3]) : "r"(addr));
}
#define MMA16816(cd, af, b0, b1)                                              \
    asm volatile("mma.sync.aligned.m16n8k16.row.col.f32.f16.f16.f32 "        \
                 "{%0,%1,%2,%3}, {%4,%5,%6,%7}, {%8,%9}, {%0,%1,%2,%3};"      \
                 : "+f"((cd)[0]), "+f"((cd)[1]), "+f"((cd)[2]), "+f"((cd)[3]) \
                 : "r"((af)[0]), "r"((af)[1]), "r"((af)[2]), "r"((af)[3]),    \
                   "r"(b0), "r"(b1))

// ---------------------------------------------------------------------------
// Kernel: X fp32 -> fp16 + per-token norm + raw routing dots. One block/token.
// ---------------------------------------------------------------------------
__global__ void __launch_bounds__(256)
convx_kernel(const float* __restrict__ x, const float* __restrict__ gv) {
    const int t = blockIdx.x;
    const int tid = threadIdx.x;
    const float4* xr = (const float4*)(x + (size_t)t * D_IN);
    const float4* gv4 = (const float4*)gv;
    __half2* hp = (__half2*)(g_Xh + (size_t)t * D_IN);

    float xx = 0.f;
    float s[N_EXP];
#pragma unroll
    for (int e = 0; e < N_EXP; e++) s[e] = 0.f;

#pragma unroll
    for (int i = 0; i < 2; i++) {
        int j = tid + i * 256;             // float4 index in [0,512)
        float4 v = xr[j];
        xx += v.x * v.x + v.y * v.y + v.z * v.z + v.w * v.w;
        hp[j * 2 + 0] = __half2(__float2half(v.x), __float2half(v.y));
        hp[j * 2 + 1] = __half2(__float2half(v.z), __float2half(v.w));
#pragma unroll
        for (int e = 0; e < N_EXP; e++) {
            float4 g = gv4[e * 512 + j];
            s[e] += v.x * g.x + v.y * g.y + v.z * g.z + v.w * g.w;
        }
    }
#pragma unroll
    for (int off = 16; off > 0; off >>= 1) {
        xx += __shfl_down_sync(0xFFFFFFFFu, xx, off);
#pragma unroll
        for (int e = 0; e < N_EXP; e++)
            s[e] += __shfl_down_sync(0xFFFFFFFFu, s[e], off);
    }
    __shared__ float sm[8][N_EXP + 1];
    int w = tid >> 5, l = tid & 31;
    if (l == 0) {
        sm[w][0] = xx;
#pragma unroll
        for (int e = 0; e < N_EXP; e++) sm[w][e + 1] = s[e];
    }
    __syncthreads();
    if (tid < N_EXP + 1) {
        float acc = 0.f;
#pragma unroll
        for (int ww = 0; ww < 8; ww++) acc += sm[ww][tid];
        if (tid == 0) g_xnorm[t] = sqrtf(acc) + EPSV;
        else          g_dots[t * N_EXP + (tid - 1)] = acc;
    }
}

// ---------------------------------------------------------------------------
// Kernel: generic fp32 -> fp16 conversion
// ---------------------------------------------------------------------------
__global__ void convh_kernel(const float* __restrict__ src,
                             __half* __restrict__ dst, int n4) {
    int i = blockIdx.x * blockDim.x + threadIdx.x;
    if (i >= n4) return;
    float4 v = ((const float4*)src)[i];
    __half2* dp = (__half2*)dst;
    dp[2 * i + 0] = __half2(__float2half(v.x), __float2half(v.y));
    dp[2 * i + 1] = __half2(__float2half(v.z), __float2half(v.w));
}

// ---------------------------------------------------------------------------
// Kernel: gate vector norms
// ---------------------------------------------------------------------------
__global__ void gnorm_kernel(const float* __restrict__ gv) {
    int e = blockIdx.x;
    float s = 0.f;
    for (int j = threadIdx.x; j < D_IN; j += 256) {
        float v = gv[e * D_IN + j];
        s += v * v;
    }
    __shared__ float red[256];
    red[threadIdx.x] = s;
    __syncthreads();
    for (int st = 128; st > 0; st >>= 1) {
        if (threadIdx.x < st) red[threadIdx.x] += red[threadIdx.x + st];
        __syncthreads();
    }
    if (threadIdx.x == 0) g_gnorm[e] = sqrtf(red[0]) + EPSV;
}

// ---------------------------------------------------------------------------
// Kernel: top-2 + softmax per token (one thread per token)
// ---------------------------------------------------------------------------
__global__ void __launch_bounds__(256)
topk_kernel(const float* __restrict__ alphas) {
    int t = blockIdx.x * 256 + threadIdx.x;
    if (t >= T_MAX) return;

    float inv = 1.f / (g_xnorm[t] * sqrtf((float)D_IN));
    float sc[N_EXP];
#pragma unroll
    for (int e = 0; e < N_EXP; e++)
        sc[e] = g_dots[t * N_EXP + e] * inv / g_gnorm[e];

    int i0 = 0;
#pragma unroll
    for (int e = 1; e < N_EXP; e++) if (sc[e] > sc[i0]) i0 = e;
    int i1 = (i0 == 0) ? 1 : 0;
#pragma unroll
    for (int e = 0; e < N_EXP; e++)
        if (e != i0 && sc[e] > sc[i1]) i1 = e;

    float e1 = expf(sc[i1] - sc[i0]);
    float denom = 1.f + e1;
    g_idx[t * 2 + 0] = i0;
    g_idx[t * 2 + 1] = i1;
    g_w[t * 2 + 0] = (1.f / denom) * alphas[i0] * (1.f / (float)RANK);
    g_w[t * 2 + 1] = (e1 / denom) * alphas[i1] * (1.f / (float)RANK);
}

// ---------------------------------------------------------------------------
// Kernel: out[t,o] += bias[o] + sum_k w_k * (B[e_k,o,:] . midd[t, e_k*16+:])
// Warp per token; lanes sweep 32 consecutive outputs -> coalesced B/out.
// 8 warps/block, grid T/8.
// ---------------------------------------------------------------------------
__global__ void __launch_bounds__(256)
lora_kernel(const float* __restrict__ B,
            const float* __restrict__ bias,
            float* __restrict__ out) {
    const int w = threadIdx.x >> 5;
    const int lane = threadIdx.x & 31;
    const int t = blockIdx.x * 8 + w;

    const int e0 = g_idx[t * 2 + 0];
    const int e1 = g_idx[t * 2 + 1];
    const float w0 = g_w[t * 2 + 0];
    const float w1 = g_w[t * 2 + 1];
    const float* B0 = B + (size_t)e0 * D_OUT * RANK;
    const float* B1 = B + (size_t)e1 * D_OUT * RANK;

    float m0[RANK], m1[RANK];
    const float4* mp0 = (const float4*)(g_midd + (size_t)t * 256 + e0 * RANK);
    const float4* mp1 = (const float4*)(g_midd + (size_t)t * 256 + e1 * RANK);
#pragma unroll
    for (int q = 0; q < 4; q++) {
        ((float4*)m0)[q] = mp0[q];
        ((float4*)m1)[q] = mp1[q];
    }

    float* orow = out + (size_t)t * D_OUT;
#pragma unroll 4
    for (int i = 0; i < D_OUT / 32; i++) {
        int o = i * 32 + lane;
        const float4* b0 = (const float4*)(B0 + (size_t)o * RANK);
        const float4* b1 = (const float4*)(B1 + (size_t)o * RANK);
        float a0 = 0.f, a1 = 0.f;
#pragma unroll
        for (int q = 0; q < 4; q++) {
            float4 v0 = b0[q];
            float4 v1 = b1[q];
            a0 += v0.x * m0[q * 4 + 0] + v0.y * m0[q * 4 + 1]
                + v0.z * m0[q * 4 + 2] + v0.w * m0[q * 4 + 3];
            a1 += v1.x * m1[q * 4 + 0] + v1.y * m1[q * 4 + 1]
                + v1.z * m1[q * 4 + 2] + v1.w * m1[q * 4 + 3];
        }
        orow[o] += bias[o] + w0 * a0 + w1 * a1;
    }
}

// ---------------------------------------------------------------------------
// Fused fp16 mma.sync GEMM over WA = [W ; A]:
//   col-blocks 0..15 -> out  = X @ W^T   (overwrite, ld=2048)
//   col-blocks 16,17 -> midd = X @ A^T   (overwrite, ld=256)
// 256 threads (8 warps, 2x4, warp tile 64x32), BK=32, 4-stage cp.async,
// 2 smem tiles/stage (Xh, WA) = 16KB -> 64KB total, 2 CTAs/SM.
// ---------------------------------------------------------------------------
#define BM 128
#define BN 128
#define BK 32
#define KITERS (D_IN / BK)          // 64
#define NSTAGE 4
#define STAGE_BYTES (2 * 128 * 64)  // 16KB
#define GEMM_SMEM (NSTAGE * STAGE_BYTES + 1024)
#define TILE_XH 0
#define TILE_WA 8192

__device__ __forceinline__ uint32_t swz_off(int row, int chunk) {
    int s = (row & 3) ^ ((row >> 2) & 1);
    return (uint32_t)(row * 64 + ((chunk ^ s) << 4));
}

__global__ void __launch_bounds__(256, 2)
gemm_fused_kernel(float* __restrict__ out, float* __restrict__ midd) {
    extern __shared__ char dsm[];
    const uint32_t sbase = (smem_u32(dsm) + 1023) & ~1023u;

    const int tid = threadIdx.x;
    const int wid = tid >> 5;
    const int lane = tid & 31;
    const int bm = blockIdx.y * BM;
    const int bnr = blockIdx.x * BN;      // row base into WA
    const int wm = (wid & 1) * 64;
    const int wn = (wid >> 1) * 32;

    const int lrA = (lane & 7) | (((lane >> 3) & 1) << 3);
    const int ksA = (lane >> 4) & 1;
    const int lrB = (lane & 7) | (((lane >> 4) & 1) << 3);
    const int ksB = (lane >> 3) & 1;

    float acc[4][4][4];
#pragma unroll
    for (int i = 0; i < 4; i++)
#pragma unroll
        for (int j = 0; j < 4; j++)
#pragma unroll
            for (int q = 0; q < 4; q++) acc[i][j][q] = 0.f;

#define ISSUE_STAGE(stg, ko_)                                                  \
    do {                                                                       \
        const int kk_ = (ko_) * BK;                                            \
        const uint32_t sb_ = sbase + (stg) * STAGE_BYTES;                      \
        _Pragma("unroll")                                                      \
        for (int i_ = 0; i_ < 4; i_++) {                                       \
            int c_ = tid + i_ * 256;   /* [0,1024) */                          \
            int tile_ = c_ >> 9;                                               \
            int row_ = (c_ >> 2) & 127;                                        \
            int cc_ = c_ & 3;                                                  \
            const __half* srcb_ = (tile_ == 0) ? (g_Xh + (size_t)(bm + row_) * D_IN) \
                                               : (g_WA + (size_t)(bnr + row_) * D_IN); \
            cp16(sb_ + tile_ * 8192 + swz_off(row_, cc_),                      \
                 srcb_ + kk_ + cc_ * 8);                                       \
        }                                                                      \
    } while (0)

    ISSUE_STAGE(0, 0);
    asm volatile("cp.async.commit_group;" ::: "memory");
    ISSUE_STAGE(1, 1);
    asm volatile("cp.async.commit_group;" ::: "memory");
    ISSUE_STAGE(2, 2);
    asm volatile("cp.async.commit_group;" ::: "memory");

    for (int ko = 0; ko < KITERS; ko++) {
        asm volatile("cp.async.wait_group 2;" ::: "memory");
        __syncthreads();

        if (ko + 3 < KITERS) ISSUE_STAGE((ko + 3) % NSTAGE, ko + 3);
        asm volatile("cp.async.commit_group;" ::: "memory");

        const uint32_t sb = sbase + (ko % NSTAGE) * STAGE_BYTES;
#pragma unroll
        for (int k16 = 0; k16 < BK; k16 += 16) {
            uint32_t axh[4][4], bwh[2][4];
            const int chA = (k16 >> 3) + ksA;
            const int chB = (k16 >> 3) + ksB;
#pragma unroll
            for (int mt = 0; mt < 4; mt++) {
                int row = wm + mt * 16 + lrA;
                ldsm_x4(axh[mt], sb + TILE_XH + swz_off(row, chA));
            }
#pragma unroll
            for (int nt2 = 0; nt2 < 2; nt2++) {
                int row = wn + nt2 * 16 + lrB;
                ldsm_x4(bwh[nt2], sb + TILE_WA + swz_off(row, chB));
            }
#pragma unroll
            for (int mt = 0; mt < 4; mt++) {
#pragma unroll
                for (int nt = 0; nt < 4; nt++) {
                    uint32_t* bh = &bwh[nt >> 1][(nt & 1) * 2];
                    MMA16816(acc[mt][nt], axh[mt], bh[0], bh[1]);
                }
            }
        }
    }

    // epilogue: route to out or midd (overwrite both)
    float* dst;
    int ld, colbase;
    if (blockIdx.x < 16) {
        dst = out; ld = D_OUT; colbase = blockIdx.x * BN;
    } else {
        dst = midd; ld = 256; colbase = (blockIdx.x - 16) * BN;
    }
#pragma unroll
    for (int mt = 0; mt < 4; mt++) {
#pragma unroll
        for (int nt = 0; nt < 4; nt++) {
            int row = bm + wm + mt * 16 + (lane >> 2);
            int col = colbase + wn + nt * 8 + (lane & 3) * 2;
            *(float2*)(dst + (size_t)row * ld + col) =
                make_float2(acc[mt][nt][0], acc[mt][nt][1]);
            *(float2*)(dst + (size_t)(row + 8) * ld + col) =
                make_float2(acc[mt][nt][2], acc[mt][nt][3]);
        }
    }
#undef ISSUE_STAGE
}

// ---------------------------------------------------------------------------
// Launch  (order chosen so the GEMM is the 4th launch -> ncu captures it)
// ---------------------------------------------------------------------------
extern "C" void kernel_launch(void* const* d_in, const int* in_sizes, int n_in,
                              void* d_out, int out_size) {
    const float* x  = (const float*)d_in[0];
    const float* Wm = (const float*)d_in[1];
    const float* bb = (const float*)d_in[2];
    const float* A  = (const float*)d_in[3];
    const float* B  = (const float*)d_in[4];
    const float* gv = (const float*)d_in[5];
    const float* al = (const float*)d_in[6];
    float* out = (float*)d_out;

    int T = in_sizes[0] / D_IN;   // 8192

    static bool init_done = false;
    static __half* wa;
    static float* midd;
    if (!init_done) {
        cudaFuncSetAttribute(gemm_fused_kernel,
                             cudaFuncAttributeMaxDynamicSharedMemorySize,
                             GEMM_SMEM);
        cudaGetSymbolAddress((void**)&wa, g_WA);
        cudaGetSymbolAddress((void**)&midd, g_midd);
        init_done = true;
    }

    // 1,2: weight conversions
    convh_kernel<<<(D_OUT * D_IN / 4 + 255) / 256, 256>>>(Wm, wa, D_OUT * D_IN / 4);
    convh_kernel<<<(N_EXP * RANK * D_IN / 4 + 255) / 256, 256>>>(
        A, wa + (size_t)D_OUT * D_IN, N_EXP * RANK * D_IN / 4);
    // 3: X conversion + xnorm + routing dots
    convx_kernel<<<T, 256>>>(x, gv);
    // 4: fused GEMM  (out = X @ W^T ; midd = X @ A^T)
    gemm_fused_kernel<<<dim3(N_WA / BN, T / BM), 256, GEMM_SMEM>>>(out, midd);
    // 5,6: routing finalize
    gnorm_kernel<<<N_EXP, 256>>>(gv);
    topk_kernel<<<(T + 255) / 256, 256>>>(al);
    // 7: out += bias + weighted LoRA contribution
    lora_kernel<<<T / 8, 256>>>(B, bb, out);
}

// round 7
// speedup vs baseline: 5.3899x; 1.5501x over previous
#include <cuda_runtime.h>
#include <cuda_fp16.h>
#include <math.h>
#include <stdint.h>

// ---------------------------------------------------------------------------
// Shapes (fixed): x [4,2048,2048] -> T=8192, d=2048 ; base_W [2048,2048];
// base_b [2048]; A [16,16,2048]; B [16,2048,16]; gate_v [16,2048];
// alphas[16]; top_k=2
// ---------------------------------------------------------------------------

#define D_IN   2048
#define D_OUT  2048
#define N_EXP  16
#define RANK   16
#define T_MAX  8192
#define EPSV   1e-6f
#define N_WA   (D_OUT + N_EXP * RANK)   // 2304 rows: W then A
#define KLORA  (N_EXP * RANK)           // 256

// Scratch (static device memory -- no allocation)
__device__ float g_gnorm[N_EXP];
__device__ float g_xnorm[T_MAX];
__device__ float g_dots[T_MAX * N_EXP];
__device__ int   g_idx[T_MAX * 2];
__device__ float g_w[T_MAX * 2];
__device__ float g_midd[(size_t)T_MAX * KLORA];   // dense mid: [T, E*RANK]

// fp16 operands
__device__ __half g_Xh[(size_t)T_MAX * D_IN];
__device__ __half g_WA[(size_t)N_WA * D_IN];      // rows 0..2047: W, 2048..: A
__device__ __half g_Mw[(size_t)T_MAX * KLORA];    // weighted mid (sparse-dense)
__device__ __half g_Bh[(size_t)D_OUT * KLORA];    // Bflat[o, e*16+r]

// ---------------------------------------------------------------------------
// PTX helpers (sm_80-era: cp.async, ldmatrix, mma.sync)
// ---------------------------------------------------------------------------
__device__ __forceinline__ uint32_t smem_u32(const void* p) {
    uint32_t a;
    asm("{ .reg .u64 t; cvta.to.shared.u64 t, %1; cvt.u32.u64 %0, t; }"
        : "=r"(a) : "l"(p));
    return a;
}
__device__ __forceinline__ void cp16(uint32_t dst, const void* src) {
    asm volatile("cp.async.cg.shared.global [%0], [%1], 16;" :: "r"(dst), "l"(src));
}
__device__ __forceinline__ void ldsm_x4(uint32_t* r, uint32_t addr) {
    asm volatile("ldmatrix.sync.aligned.m8n8.x4.shared.b16 {%0,%1,%2,%3}, [%4];"
                 : "=r"(r[0]), "=r"(r[1]), "=r"(r[2]), "=r"(r[3]) : "r"(addr));
}
#define MMA16816(cd, af, b0, b1)                                              \
    asm volatile("mma.sync.aligned.m16n8k16.row.col.f32.f16.f16.f32 "        \
                 "{%0,%1,%2,%3}, {%4,%5,%6,%7}, {%8,%9}, {%0,%1,%2,%3};"      \
                 : "+f"((cd)[0]), "+f"((cd)[1]), "+f"((cd)[2]), "+f"((cd)[3]) \
                 : "r"((af)[0]), "r"((af)[1]), "r"((af)[2]), "r"((af)[3]),    \
                   "r"(b0), "r"(b1))

// ---------------------------------------------------------------------------
// Kernel: X fp32 -> fp16 + per-token norm + raw routing dots. One block/token.
// ---------------------------------------------------------------------------
__global__ void __launch_bounds__(256)
convx_kernel(const float* __restrict__ x, const float* __restrict__ gv) {
    const int t = blockIdx.x;
    const int tid = threadIdx.x;
    const float4* xr = (const float4*)(x + (size_t)t * D_IN);
    const float4* gv4 = (const float4*)gv;
    __half2* hp = (__half2*)(g_Xh + (size_t)t * D_IN);

    float xx = 0.f;
    float s[N_EXP];
#pragma unroll
    for (int e = 0; e < N_EXP; e++) s[e] = 0.f;

#pragma unroll
    for (int i = 0; i < 2; i++) {
        int j = tid + i * 256;
        float4 v = xr[j];
        xx += v.x * v.x + v.y * v.y + v.z * v.z + v.w * v.w;
        hp[j * 2 + 0] = __half2(__float2half(v.x), __float2half(v.y));
        hp[j * 2 + 1] = __half2(__float2half(v.z), __float2half(v.w));
#pragma unroll
        for (int e = 0; e < N_EXP; e++) {
            float4 g = gv4[e * 512 + j];
            s[e] += v.x * g.x + v.y * g.y + v.z * g.z + v.w * g.w;
        }
    }
#pragma unroll
    for (int off = 16; off > 0; off >>= 1) {
        xx += __shfl_down_sync(0xFFFFFFFFu, xx, off);
#pragma unroll
        for (int e = 0; e < N_EXP; e++)
            s[e] += __shfl_down_sync(0xFFFFFFFFu, s[e], off);
    }
    __shared__ float sm[8][N_EXP + 1];
    int w = tid >> 5, l = tid & 31;
    if (l == 0) {
        sm[w][0] = xx;
#pragma unroll
        for (int e = 0; e < N_EXP; e++) sm[w][e + 1] = s[e];
    }
    __syncthreads();
    if (tid < N_EXP + 1) {
        float acc = 0.f;
#pragma unroll
        for (int ww = 0; ww < 8; ww++) acc += sm[ww][tid];
        if (tid == 0) g_xnorm[t] = sqrtf(acc) + EPSV;
        else          g_dots[t * N_EXP + (tid - 1)] = acc;
    }
}

// ---------------------------------------------------------------------------
// Kernel: generic fp32 -> fp16 conversion
// ---------------------------------------------------------------------------
__global__ void convh_kernel(const float* __restrict__ src,
                             __half* __restrict__ dst, int n4) {
    int i = blockIdx.x * blockDim.x + threadIdx.x;
    if (i >= n4) return;
    float4 v = ((const float4*)src)[i];
    __half2* dp = (__half2*)dst;
    dp[2 * i + 0] = __half2(__float2half(v.x), __float2half(v.y));
    dp[2 * i + 1] = __half2(__float2half(v.z), __float2half(v.w));
}

// ---------------------------------------------------------------------------
// Kernel: transpose B [E, d_out, r] -> Bh [d_out, E*r] fp16
// thread gidx = o*16 + e; copies 16 contiguous floats.
// ---------------------------------------------------------------------------
__global__ void __launch_bounds__(256)
convB_kernel(const float* __restrict__ B) {
    int gidx = blockIdx.x * 256 + threadIdx.x;   // [0, 32768)
    int o = gidx >> 4;
    int e = gidx & 15;
    const float4* src = (const float4*)(B + ((size_t)e * D_OUT + o) * RANK);
    __half2 buf[8];
#pragma unroll
    for (int q = 0; q < 4; q++) {
        float4 v = src[q];
        buf[q * 2 + 0] = __half2(__float2half(v.x), __float2half(v.y));
        buf[q * 2 + 1] = __half2(__float2half(v.z), __float2half(v.w));
    }
    uint4* dst = (uint4*)(g_Bh + (size_t)o * KLORA + e * RANK);
    dst[0] = ((uint4*)buf)[0];
    dst[1] = ((uint4*)buf)[1];
}

// ---------------------------------------------------------------------------
// Kernel: gate vector norms
// ---------------------------------------------------------------------------
__global__ void gnorm_kernel(const float* __restrict__ gv) {
    int e = blockIdx.x;
    float s = 0.f;
    for (int j = threadIdx.x; j < D_IN; j += 256) {
        float v = gv[e * D_IN + j];
        s += v * v;
    }
    __shared__ float red[256];
    red[threadIdx.x] = s;
    __syncthreads();
    for (int st = 128; st > 0; st >>= 1) {
        if (threadIdx.x < st) red[threadIdx.x] += red[threadIdx.x + st];
        __syncthreads();
    }
    if (threadIdx.x == 0) g_gnorm[e] = sqrtf(red[0]) + EPSV;
}

// ---------------------------------------------------------------------------
// Kernel: top-2 + softmax per token (one thread per token)
// ---------------------------------------------------------------------------
__global__ void __launch_bounds__(256)
topk_kernel(const float* __restrict__ alphas) {
    int t = blockIdx.x * 256 + threadIdx.x;
    if (t >= T_MAX) return;

    float inv = 1.f / (g_xnorm[t] * sqrtf((float)D_IN));
    float sc[N_EXP];
#pragma unroll
    for (int e = 0; e < N_EXP; e++)
        sc[e] = g_dots[t * N_EXP + e] * inv / g_gnorm[e];

    int i0 = 0;
#pragma unroll
    for (int e = 1; e < N_EXP; e++) if (sc[e] > sc[i0]) i0 = e;
    int i1 = (i0 == 0) ? 1 : 0;
#pragma unroll
    for (int e = 0; e < N_EXP; e++)
        if (e != i0 && sc[e] > sc[i1]) i1 = e;

    float e1 = expf(sc[i1] - sc[i0]);
    float denom = 1.f + e1;
    g_idx[t * 2 + 0] = i0;
    g_idx[t * 2 + 1] = i1;
    g_w[t * 2 + 0] = (1.f / denom) * alphas[i0] * (1.f / (float)RANK);
    g_w[t * 2 + 1] = (e1 / denom) * alphas[i1] * (1.f / (float)RANK);
}

// ---------------------------------------------------------------------------
// Kernel: midw[t, e*16+r] = w_{t,k} * midd[t, e*16+r] for selected experts,
// 0 elsewhere. 32 tokens/block; 8 threads per token, 32 halves each.
// ---------------------------------------------------------------------------
__global__ void __launch_bounds__(256)
midw_kernel() {
    const int t = blockIdx.x * 32 + (threadIdx.x >> 3);
    const int j = threadIdx.x & 7;            // covers halves [j*32, j*32+32)
    const int e0 = g_idx[t * 2 + 0];
    const int e1 = g_idx[t * 2 + 1];
    const float w0 = g_w[t * 2 + 0];
    const float w1 = g_w[t * 2 + 1];
    const float* mrow = g_midd + (size_t)t * KLORA;

    __half2 buf[16];
    const int p0 = j * 32;
#pragma unroll
    for (int q = 0; q < 16; q++) {
        int p = p0 + q * 2;
        int ea = p >> 4;               // same expert for p and p+1 (16-aligned)
        float va = 0.f, vb = 0.f;
        if (ea == e0)      { va = w0 * mrow[p]; vb = w0 * mrow[p + 1]; }
        else if (ea == e1) { va = w1 * mrow[p]; vb = w1 * mrow[p + 1]; }
        buf[q] = __half2(__float2half(va), __float2half(vb));
    }
    uint4* dst = (uint4*)(g_Mw + (size_t)t * KLORA + p0);
#pragma unroll
    for (int q = 0; q < 4; q++) dst[q] = ((uint4*)buf)[q];
}

// ---------------------------------------------------------------------------
// Templated fp16 mma.sync GEMM, 128x128 CTA tile, BK=32, 4-stage cp.async.
// MODE 0 (KLEN=2048): Bop=WA; col-blocks 0..15 -> out (overwrite, ld 2048),
//                     16,17 -> midd (overwrite, ld 256).
// MODE 1 (KLEN=256):  out[tile] += acc + bias[col]   (LoRA combine GEMM)
// ---------------------------------------------------------------------------
#define BM 128
#define BN 128
#define BK 32
#define NSTAGE 4
#define STAGE_BYTES (2 * 128 * 64)  // 16KB
#define GEMM_SMEM (NSTAGE * STAGE_BYTES + 1024)
#define TILE_A 0
#define TILE_B 8192

__device__ __forceinline__ uint32_t swz_off(int row, int chunk) {
    int s = (row & 3) ^ ((row >> 2) & 1);
    return (uint32_t)(row * 64 + ((chunk ^ s) << 4));
}

template <int KLEN, int MODE>
__global__ void __launch_bounds__(256, 2)
gemm_tpl(const __half* __restrict__ Aop, const __half* __restrict__ Bop,
         float* __restrict__ out, float* __restrict__ midd,
         const float* __restrict__ bias) {
    constexpr int KITERS = KLEN / BK;
    extern __shared__ char dsm[];
    const uint32_t sbase = (smem_u32(dsm) + 1023) & ~1023u;

    const int tid = threadIdx.x;
    const int wid = tid >> 5;
    const int lane = tid & 31;
    const int bm = blockIdx.y * BM;
    const int bnr = blockIdx.x * BN;
    const int wm = (wid & 1) * 64;
    const int wn = (wid >> 1) * 32;

    const int lrA = (lane & 7) | (((lane >> 3) & 1) << 3);
    const int ksA = (lane >> 4) & 1;
    const int lrB = (lane & 7) | (((lane >> 4) & 1) << 3);
    const int ksB = (lane >> 3) & 1;

    float acc[4][4][4];
#pragma unroll
    for (int i = 0; i < 4; i++)
#pragma unroll
        for (int j = 0; j < 4; j++)
#pragma unroll
            for (int q = 0; q < 4; q++) acc[i][j][q] = 0.f;

#define ISSUE_STAGE(stg, ko_)                                                  \
    do {                                                                       \
        const int kk_ = (ko_) * BK;                                            \
        const uint32_t sb_ = sbase + (stg) * STAGE_BYTES;                      \
        _Pragma("unroll")                                                      \
        for (int i_ = 0; i_ < 4; i_++) {                                       \
            int c_ = tid + i_ * 256;                                           \
            int tile_ = c_ >> 9;                                               \
            int row_ = (c_ >> 2) & 127;                                        \
            int cc_ = c_ & 3;                                                  \
            const __half* srcb_ = (tile_ == 0)                                 \
                ? (Aop + (size_t)(bm + row_) * KLEN)                           \
                : (Bop + (size_t)(bnr + row_) * KLEN);                         \
            cp16(sb_ + tile_ * 8192 + swz_off(row_, cc_),                      \
                 srcb_ + kk_ + cc_ * 8);                                       \
        }                                                                      \
    } while (0)

    ISSUE_STAGE(0, 0);
    asm volatile("cp.async.commit_group;" ::: "memory");
    ISSUE_STAGE(1, 1);
    asm volatile("cp.async.commit_group;" ::: "memory");
    ISSUE_STAGE(2, 2);
    asm volatile("cp.async.commit_group;" ::: "memory");

    for (int ko = 0; ko < KITERS; ko++) {
        asm volatile("cp.async.wait_group 2;" ::: "memory");
        __syncthreads();

        if (ko + 3 < KITERS) ISSUE_STAGE((ko + 3) % NSTAGE, ko + 3);
        asm volatile("cp.async.commit_group;" ::: "memory");

        const uint32_t sb = sbase + (ko % NSTAGE) * STAGE_BYTES;
#pragma unroll
        for (int k16 = 0; k16 < BK; k16 += 16) {
            uint32_t axh[4][4], bwh[2][4];
            const int chA = (k16 >> 3) + ksA;
            const int chB = (k16 >> 3) + ksB;
#pragma unroll
            for (int mt = 0; mt < 4; mt++) {
                int row = wm + mt * 16 + lrA;
                ldsm_x4(axh[mt], sb + TILE_A + swz_off(row, chA));
            }
#pragma unroll
            for (int nt2 = 0; nt2 < 2; nt2++) {
                int row = wn + nt2 * 16 + lrB;
                ldsm_x4(bwh[nt2], sb + TILE_B + swz_off(row, chB));
            }
#pragma unroll
            for (int mt = 0; mt < 4; mt++) {
#pragma unroll
                for (int nt = 0; nt < 4; nt++) {
                    uint32_t* bh = &bwh[nt >> 1][(nt & 1) * 2];
                    MMA16816(acc[mt][nt], axh[mt], bh[0], bh[1]);
                }
            }
        }
    }

    if (MODE == 0) {
        float* dst;
        int ld, colbase;
        if (blockIdx.x < 16) {
            dst = out; ld = D_OUT; colbase = blockIdx.x * BN;
        } else {
            dst = midd; ld = KLORA; colbase = (blockIdx.x - 16) * BN;
        }
#pragma unroll
        for (int mt = 0; mt < 4; mt++) {
#pragma unroll
            for (int nt = 0; nt < 4; nt++) {
                int row = bm + wm + mt * 16 + (lane >> 2);
                int col = colbase + wn + nt * 8 + (lane & 3) * 2;
                *(float2*)(dst + (size_t)row * ld + col) =
                    make_float2(acc[mt][nt][0], acc[mt][nt][1]);
                *(float2*)(dst + (size_t)(row + 8) * ld + col) =
                    make_float2(acc[mt][nt][2], acc[mt][nt][3]);
            }
        }
    } else {
        const int colbase = blockIdx.x * BN;
#pragma unroll
        for (int mt = 0; mt < 4; mt++) {
#pragma unroll
            for (int nt = 0; nt < 4; nt++) {
                int row = bm + wm + mt * 16 + (lane >> 2);
                int col = colbase + wn + nt * 8 + (lane & 3) * 2;
                float bx = bias[col], by = bias[col + 1];
                float2* p0 = (float2*)(out + (size_t)row * D_OUT + col);
                float2 v0 = *p0;
                v0.x += acc[mt][nt][0] + bx;
                v0.y += acc[mt][nt][1] + by;
                *p0 = v0;
                float2* p1 = (float2*)(out + (size_t)(row + 8) * D_OUT + col);
                float2 v1 = *p1;
                v1.x += acc[mt][nt][2] + bx;
                v1.y += acc[mt][nt][3] + by;
                *p1 = v1;
            }
        }
    }
#undef ISSUE_STAGE
}

// ---------------------------------------------------------------------------
// Launch  (GEMM1 kept as 4th launch for ncu capture)
// ---------------------------------------------------------------------------
extern "C" void kernel_launch(void* const* d_in, const int* in_sizes, int n_in,
                              void* d_out, int out_size) {
    const float* x  = (const float*)d_in[0];
    const float* Wm = (const float*)d_in[1];
    const float* bb = (const float*)d_in[2];
    const float* A  = (const float*)d_in[3];
    const float* B  = (const float*)d_in[4];
    const float* gv = (const float*)d_in[5];
    const float* al = (const float*)d_in[6];
    float* out = (float*)d_out;

    int T = in_sizes[0] / D_IN;   // 8192

    static bool init_done = false;
    static __half *xh, *wa, *mw, *bh;
    static float* midd;
    if (!init_done) {
        cudaFuncSetAttribute(gemm_tpl<2048, 0>,
                             cudaFuncAttributeMaxDynamicSharedMemorySize,
                             GEMM_SMEM);
        cudaFuncSetAttribute(gemm_tpl<256, 1>,
                             cudaFuncAttributeMaxDynamicSharedMemorySize,
                             GEMM_SMEM);
        cudaGetSymbolAddress((void**)&xh, g_Xh);
        cudaGetSymbolAddress((void**)&wa, g_WA);
        cudaGetSymbolAddress((void**)&mw, g_Mw);
        cudaGetSymbolAddress((void**)&bh, g_Bh);
        cudaGetSymbolAddress((void**)&midd, g_midd);
        init_done = true;
    }

    // 1,2: weight conversions
    convh_kernel<<<(D_OUT * D_IN / 4 + 255) / 256, 256>>>(Wm, wa, D_OUT * D_IN / 4);
    convh_kernel<<<(N_EXP * RANK * D_IN / 4 + 255) / 256, 256>>>(
        A, wa + (size_t)D_OUT * D_IN, N_EXP * RANK * D_IN / 4);
    // 3: X conversion + xnorm + routing dots
    convx_kernel<<<T, 256>>>(x, gv);
    // 4: fused GEMM  (out = X @ W^T ; midd = X @ A^T)
    gemm_tpl<2048, 0><<<dim3(N_WA / BN, T / BM), 256, GEMM_SMEM>>>(
        xh, wa, out, midd, nullptr);
    // 5-8: routing finalize + LoRA operand prep
    gnorm_kernel<<<N_EXP, 256>>>(gv);
    topk_kernel<<<(T + 255) / 256, 256>>>(al);
    midw_kernel<<<T / 32, 256>>>();
    convB_kernel<<<D_OUT * N_EXP / 256, 256>>>(B);
    // 9: out += midw @ Bh^T + bias
    gemm_tpl<256, 1><<<dim3(D_OUT / BN, T / BM), 256, GEMM_SMEM>>>(
        mw, bh, out, nullptr, bb);
}

// round 8
// speedup vs baseline: 5.5320x; 1.0264x over previous
#include <cuda_runtime.h>
#include <cuda_fp16.h>
#include <math.h>
#include <stdint.h>

// ---------------------------------------------------------------------------
// Shapes (fixed): x [4,2048,2048] -> T=8192, d=2048 ; base_W [2048,2048];
// base_b [2048]; A [16,16,2048]; B [16,2048,16]; gate_v [16,2048];
// alphas[16]; top_k=2
// ---------------------------------------------------------------------------

#define D_IN   2048
#define D_OUT  2048
#define N_EXP  16
#define RANK   16
#define T_MAX  8192
#define EPSV   1e-6f
#define N_WA   (D_OUT + N_EXP * RANK)   // 2304 rows: W then A
#define KLORA  (N_EXP * RANK)           // 256

// Scratch (static device memory -- no allocation)
__device__ float g_gnorm[N_EXP];
__device__ float g_xnorm[T_MAX];
__device__ float g_dots[T_MAX * N_EXP];
__device__ int   g_idx[T_MAX * 2];
__device__ float g_w[T_MAX * 2];
__device__ float g_midd[(size_t)T_MAX * KLORA];   // dense mid: [T, E*RANK]

// fp16 operands
__device__ __half g_Xh[(size_t)T_MAX * D_IN];
__device__ __half g_WA[(size_t)N_WA * D_IN];      // rows 0..2047: W, 2048..: A
__device__ __half g_Mw[(size_t)T_MAX * KLORA];    // weighted mid
__device__ __half g_Bh[(size_t)D_OUT * KLORA];    // Bflat[o, e*16+r]

// ---------------------------------------------------------------------------
// PTX helpers
// ---------------------------------------------------------------------------
__device__ __forceinline__ uint32_t smem_u32(const void* p) {
    uint32_t a;
    asm("{ .reg .u64 t; cvta.to.shared.u64 t, %1; cvt.u32.u64 %0, t; }"
        : "=r"(a) : "l"(p));
    return a;
}
__device__ __forceinline__ void cp16(uint32_t dst, const void* src) {
    asm volatile("cp.async.cg.shared.global [%0], [%1], 16;" :: "r"(dst), "l"(src));
}
__device__ __forceinline__ void ldsm_x4(uint32_t* r, uint32_t addr) {
    asm volatile("ldmatrix.sync.aligned.m8n8.x4.shared.b16 {%0,%1,%2,%3}, [%4];"
                 : "=r"(r[0]), "=r"(r[1]), "=r"(r[2]), "=r"(r[3]) : "r"(addr));
}
#define MMA16816(cd, af, b0, b1)                                              \
    asm volatile("mma.sync.aligned.m16n8k16.row.col.f32.f16.f16.f32 "        \
                 "{%0,%1,%2,%3}, {%4,%5,%6,%7}, {%8,%9}, {%0,%1,%2,%3};"      \
                 : "+f"((cd)[0]), "+f"((cd)[1]), "+f"((cd)[2]), "+f"((cd)[3]) \
                 : "r"((af)[0]), "r"((af)[1]), "r"((af)[2]), "r"((af)[3]),    \
                   "r"(b0), "r"(b1))

// ---------------------------------------------------------------------------
// Kernel: X fp32 -> fp16 + per-token norm + routing dots.
// 512 threads, 16 tokens/block. Staging warp = token (xnorm + fp16 convert);
// dot warp = expert with its gv row held in 64 registers; x in smem (128KB).
// ---------------------------------------------------------------------------
#define CONVX_TOKENS 16
#define CONVX_SMEM (CONVX_TOKENS * D_IN * 4)   // 128KB

__global__ void __launch_bounds__(512)
convx_kernel(const float* __restrict__ x, const float* __restrict__ gv) {
    extern __shared__ float xs[];              // [16][2048]
    const int t0 = blockIdx.x * CONVX_TOKENS;
    const int w = threadIdx.x >> 5;
    const int l = threadIdx.x & 31;

    // ---- stage: warp w handles token t0+w ----
    {
        const float4* xr = (const float4*)(x + (size_t)(t0 + w) * D_IN);
        float4* xsr = (float4*)(xs + (size_t)w * D_IN);
        __half2* hp = (__half2*)(g_Xh + (size_t)(t0 + w) * D_IN);
        float xx = 0.f;
#pragma unroll
        for (int i = 0; i < 16; i++) {
            int j = l + 32 * i;
            float4 v = xr[j];
            xsr[j] = v;
            xx += v.x * v.x + v.y * v.y + v.z * v.z + v.w * v.w;
            hp[j * 2 + 0] = __half2(__float2half(v.x), __float2half(v.y));
            hp[j * 2 + 1] = __half2(__float2half(v.z), __float2half(v.w));
        }
#pragma unroll
        for (int off = 16; off > 0; off >>= 1)
            xx += __shfl_down_sync(0xFFFFFFFFu, xx, off);
        if (l == 0) g_xnorm[t0 + w] = sqrtf(xx) + EPSV;
    }
    __syncthreads();

    // ---- dots: warp w = expert w, gv row in registers ----
    float gvr[64];
    {
        const float* gvrow = gv + (size_t)w * D_IN;
#pragma unroll
        for (int i = 0; i < 64; i++) gvr[i] = gvrow[l + 32 * i];
    }
#pragma unroll 1
    for (int t = 0; t < CONVX_TOKENS; t++) {
        const float* xt = xs + (size_t)t * D_IN;
        float s = 0.f;
#pragma unroll
        for (int i = 0; i < 64; i++) s += xt[l + 32 * i] * gvr[i];
#pragma unroll
        for (int off = 16; off > 0; off >>= 1)
            s += __shfl_down_sync(0xFFFFFFFFu, s, off);
        if (l == 0) g_dots[(size_t)(t0 + t) * N_EXP + w] = s;
    }
}

// ---------------------------------------------------------------------------
// Kernel: generic fp32 -> fp16 conversion
// ---------------------------------------------------------------------------
__global__ void convh_kernel(const float* __restrict__ src,
                             __half* __restrict__ dst, int n4) {
    int i = blockIdx.x * blockDim.x + threadIdx.x;
    if (i >= n4) return;
    float4 v = ((const float4*)src)[i];
    __half2* dp = (__half2*)dst;
    dp[2 * i + 0] = __half2(__float2half(v.x), __float2half(v.y));
    dp[2 * i + 1] = __half2(__float2half(v.z), __float2half(v.w));
}

// ---------------------------------------------------------------------------
// Kernel: transpose B [E, d_out, r] -> Bh [d_out, E*r] fp16
// ---------------------------------------------------------------------------
__global__ void __launch_bounds__(256)
convB_kernel(const float* __restrict__ B) {
    int gidx = blockIdx.x * 256 + threadIdx.x;   // [0, 32768)
    int o = gidx >> 4;
    int e = gidx & 15;
    const float4* src = (const float4*)(B + ((size_t)e * D_OUT + o) * RANK);
    __half2 buf[8];
#pragma unroll
    for (int q = 0; q < 4; q++) {
        float4 v = src[q];
        buf[q * 2 + 0] = __half2(__float2half(v.x), __float2half(v.y));
        buf[q * 2 + 1] = __half2(__float2half(v.z), __float2half(v.w));
    }
    uint4* dst = (uint4*)(g_Bh + (size_t)o * KLORA + e * RANK);
    dst[0] = ((uint4*)buf)[0];
    dst[1] = ((uint4*)buf)[1];
}

// ---------------------------------------------------------------------------
// Kernel: gate vector norms
// ---------------------------------------------------------------------------
__global__ void gnorm_kernel(const float* __restrict__ gv) {
    int e = blockIdx.x;
    float s = 0.f;
    for (int j = threadIdx.x; j < D_IN; j += 256) {
        float v = gv[e * D_IN + j];
        s += v * v;
    }
    __shared__ float red[256];
    red[threadIdx.x] = s;
    __syncthreads();
    for (int st = 128; st > 0; st >>= 1) {
        if (threadIdx.x < st) red[threadIdx.x] += red[threadIdx.x + st];
        __syncthreads();
    }
    if (threadIdx.x == 0) g_gnorm[e] = sqrtf(red[0]) + EPSV;
}

// ---------------------------------------------------------------------------
// Kernel: top-2 + softmax per token (one thread per token)
// ---------------------------------------------------------------------------
__global__ void __launch_bounds__(256)
topk_kernel(const float* __restrict__ alphas) {
    int t = blockIdx.x * 256 + threadIdx.x;
    if (t >= T_MAX) return;

    float inv = 1.f / (g_xnorm[t] * sqrtf((float)D_IN));
    float sc[N_EXP];
#pragma unroll
    for (int e = 0; e < N_EXP; e++)
        sc[e] = g_dots[t * N_EXP + e] * inv / g_gnorm[e];

    int i0 = 0;
#pragma unroll
    for (int e = 1; e < N_EXP; e++) if (sc[e] > sc[i0]) i0 = e;
    int i1 = (i0 == 0) ? 1 : 0;
#pragma unroll
    for (int e = 0; e < N_EXP; e++)
        if (e != i0 && sc[e] > sc[i1]) i1 = e;

    float e1 = expf(sc[i1] - sc[i0]);
    float denom = 1.f + e1;
    g_idx[t * 2 + 0] = i0;
    g_idx[t * 2 + 1] = i1;
    g_w[t * 2 + 0] = (1.f / denom) * alphas[i0] * (1.f / (float)RANK);
    g_w[t * 2 + 1] = (e1 / denom) * alphas[i1] * (1.f / (float)RANK);
}

// ---------------------------------------------------------------------------
// Kernel: midw[t, e*16+r] = w_{t,k} * midd[t, e*16+r] (selected), 0 else.
// ---------------------------------------------------------------------------
__global__ void __launch_bounds__(256)
midw_kernel() {
    const int t = blockIdx.x * 32 + (threadIdx.x >> 3);
    const int j = threadIdx.x & 7;
    const int e0 = g_idx[t * 2 + 0];
    const int e1 = g_idx[t * 2 + 1];
    const float w0 = g_w[t * 2 + 0];
    const float w1 = g_w[t * 2 + 1];
    const float* mrow = g_midd + (size_t)t * KLORA;

    __half2 buf[16];
    const int p0 = j * 32;
#pragma unroll
    for (int q = 0; q < 16; q++) {
        int p = p0 + q * 2;
        int ea = p >> 4;
        float va = 0.f, vb = 0.f;
        if (ea == e0)      { va = w0 * mrow[p]; vb = w0 * mrow[p + 1]; }
        else if (ea == e1) { va = w1 * mrow[p]; vb = w1 * mrow[p + 1]; }
        buf[q] = __half2(__float2half(va), __float2half(vb));
    }
    uint4* dst = (uint4*)(g_Mw + (size_t)t * KLORA + p0);
#pragma unroll
    for (int q = 0; q < 4; q++) dst[q] = ((uint4*)buf)[q];
}

// ---------------------------------------------------------------------------
// Templated fp16 mma.sync GEMM, 128x128 CTA tile, BK=32, 6-stage cp.async.
// MODE 0 (KLEN=2048): Bop=WA; col-blocks 0..15 -> out, 16,17 -> midd.
// MODE 1 (KLEN=256):  out[tile] += acc + bias[col]
// ---------------------------------------------------------------------------
#define BM 128
#define BN 128
#define BK 32
#define NSTAGE 6
#define STAGE_BYTES (2 * 128 * 64)  // 16KB
#define GEMM_SMEM (NSTAGE * STAGE_BYTES + 1024)
#define TILE_A 0
#define TILE_B 8192

__device__ __forceinline__ uint32_t swz_off(int row, int chunk) {
    int s = (row & 3) ^ ((row >> 2) & 1);
    return (uint32_t)(row * 64 + ((chunk ^ s) << 4));
}

template <int KLEN, int MODE>
__global__ void __launch_bounds__(256, 2)
gemm_tpl(const __half* __restrict__ Aop, const __half* __restrict__ Bop,
         float* __restrict__ out, float* __restrict__ midd,
         const float* __restrict__ bias) {
    constexpr int KITERS = KLEN / BK;
    extern __shared__ char dsm[];
    const uint32_t sbase = (smem_u32(dsm) + 1023) & ~1023u;

    const int tid = threadIdx.x;
    const int wid = tid >> 5;
    const int lane = tid & 31;
    const int bm = blockIdx.y * BM;
    const int bnr = blockIdx.x * BN;
    const int wm = (wid & 1) * 64;
    const int wn = (wid >> 1) * 32;

    const int lrA = (lane & 7) | (((lane >> 3) & 1) << 3);
    const int ksA = (lane >> 4) & 1;
    const int lrB = (lane & 7) | (((lane >> 4) & 1) << 3);
    const int ksB = (lane >> 3) & 1;

    float acc[4][4][4];
#pragma unroll
    for (int i = 0; i < 4; i++)
#pragma unroll
        for (int j = 0; j < 4; j++)
#pragma unroll
            for (int q = 0; q < 4; q++) acc[i][j][q] = 0.f;

#define ISSUE_STAGE(stg, ko_)                                                  \
    do {                                                                       \
        const int kk_ = (ko_) * BK;                                            \
        const uint32_t sb_ = sbase + (stg) * STAGE_BYTES;                      \
        _Pragma("unroll")                                                      \
        for (int i_ = 0; i_ < 4; i_++) {                                       \
            int c_ = tid + i_ * 256;                                           \
            int tile_ = c_ >> 9;                                               \
            int row_ = (c_ >> 2) & 127;                                        \
            int cc_ = c_ & 3;                                                  \
            const __half* srcb_ = (tile_ == 0)                                 \
                ? (Aop + (size_t)(bm + row_) * KLEN)                           \
                : (Bop + (size_t)(bnr + row_) * KLEN);                         \
            cp16(sb_ + tile_ * 8192 + swz_off(row_, cc_),                      \
                 srcb_ + kk_ + cc_ * 8);                                       \
        }                                                                      \
    } while (0)

    // prologue: fill NSTAGE-1 = 5 stages (guard against short K)
#pragma unroll
    for (int s = 0; s < NSTAGE - 1; s++) {
        if (s < KITERS) ISSUE_STAGE(s, s);
        asm volatile("cp.async.commit_group;" ::: "memory");
    }

    for (int ko = 0; ko < KITERS; ko++) {
        asm volatile("cp.async.wait_group %0;" :: "n"(NSTAGE - 2) : "memory");
        __syncthreads();

        if (ko + NSTAGE - 1 < KITERS)
            ISSUE_STAGE((ko + NSTAGE - 1) % NSTAGE, ko + NSTAGE - 1);
        asm volatile("cp.async.commit_group;" ::: "memory");

        const uint32_t sb = sbase + (ko % NSTAGE) * STAGE_BYTES;
#pragma unroll
        for (int k16 = 0; k16 < BK; k16 += 16) {
            uint32_t axh[4][4], bwh[2][4];
            const int chA = (k16 >> 3) + ksA;
            const int chB = (k16 >> 3) + ksB;
#pragma unroll
            for (int mt = 0; mt < 4; mt++) {
                int row = wm + mt * 16 + lrA;
                ldsm_x4(axh[mt], sb + TILE_A + swz_off(row, chA));
            }
#pragma unroll
            for (int nt2 = 0; nt2 < 2; nt2++) {
                int row = wn + nt2 * 16 + lrB;
                ldsm_x4(bwh[nt2], sb + TILE_B + swz_off(row, chB));
            }
#pragma unroll
            for (int mt = 0; mt < 4; mt++) {
#pragma unroll
                for (int nt = 0; nt < 4; nt++) {
                    uint32_t* bh = &bwh[nt >> 1][(nt & 1) * 2];
                    MMA16816(acc[mt][nt], axh[mt], bh[0], bh[1]);
                }
            }
        }
    }

    if (MODE == 0) {
        float* dst;
        int ld, colbase;
        if (blockIdx.x < 16) {
            dst = out; ld = D_OUT; colbase = blockIdx.x * BN;
        } else {
            dst = midd; ld = KLORA; colbase = (blockIdx.x - 16) * BN;
        }
#pragma unroll
        for (int mt = 0; mt < 4; mt++) {
#pragma unroll
            for (int nt = 0; nt < 4; nt++) {
                int row = bm + wm + mt * 16 + (lane >> 2);
                int col = colbase + wn + nt * 8 + (lane & 3) * 2;
                *(float2*)(dst + (size_t)row * ld + col) =
                    make_float2(acc[mt][nt][0], acc[mt][nt][1]);
                *(float2*)(dst + (size_t)(row + 8) * ld + col) =
                    make_float2(acc[mt][nt][2], acc[mt][nt][3]);
            }
        }
    } else {
        const int colbase = blockIdx.x * BN;
#pragma unroll
        for (int mt = 0; mt < 4; mt++) {
#pragma unroll
            for (int nt = 0; nt < 4; nt++) {
                int row = bm + wm + mt * 16 + (lane >> 2);
                int col = colbase + wn + nt * 8 + (lane & 3) * 2;
                float bx = bias[col], by = bias[col + 1];
                float2* p0 = (float2*)(out + (size_t)row * D_OUT + col);
                float2 v0 = *p0;
                v0.x += acc[mt][nt][0] + bx;
                v0.y += acc[mt][nt][1] + by;
                *p0 = v0;
                float2* p1 = (float2*)(out + (size_t)(row + 8) * D_OUT + col);
                float2 v1 = *p1;
                v1.x += acc[mt][nt][2] + bx;
                v1.y += acc[mt][nt][3] + by;
                *p1 = v1;
            }
        }
    }
#undef ISSUE_STAGE
}

// ---------------------------------------------------------------------------
// Launch  (GEMM1 kept as 4th launch for ncu capture)
// ---------------------------------------------------------------------------
extern "C" void kernel_launch(void* const* d_in, const int* in_sizes, int n_in,
                              void* d_out, int out_size) {
    const float* x  = (const float*)d_in[0];
    const float* Wm = (const float*)d_in[1];
    const float* bb = (const float*)d_in[2];
    const float* A  = (const float*)d_in[3];
    const float* B  = (const float*)d_in[4];
    const float* gv = (const float*)d_in[5];
    const float* al = (const float*)d_in[6];
    float* out = (float*)d_out;

    int T = in_sizes[0] / D_IN;   // 8192

    static bool init_done = false;
    static __half *xh, *wa, *mw, *bh;
    static float* midd;
    if (!init_done) {
        cudaFuncSetAttribute(gemm_tpl<2048, 0>,
                             cudaFuncAttributeMaxDynamicSharedMemorySize,
                             GEMM_SMEM);
        cudaFuncSetAttribute(gemm_tpl<256, 1>,
                             cudaFuncAttributeMaxDynamicSharedMemorySize,
                             GEMM_SMEM);
        cudaFuncSetAttribute(convx_kernel,
                             cudaFuncAttributeMaxDynamicSharedMemorySize,
                             CONVX_SMEM);
        cudaGetSymbolAddress((void**)&xh, g_Xh);
        cudaGetSymbolAddress((void**)&wa, g_WA);
        cudaGetSymbolAddress((void**)&mw, g_Mw);
        cudaGetSymbolAddress((void**)&bh, g_Bh);
        cudaGetSymbolAddress((void**)&midd, g_midd);
        init_done = true;
    }

    // 1,2: weight conversions
    convh_kernel<<<(D_OUT * D_IN / 4 + 255) / 256, 256>>>(Wm, wa, D_OUT * D_IN / 4);
    convh_kernel<<<(N_EXP * RANK * D_IN / 4 + 255) / 256, 256>>>(
        A, wa + (size_t)D_OUT * D_IN, N_EXP * RANK * D_IN / 4);
    // 3: X conversion + xnorm + routing dots
    convx_kernel<<<T / CONVX_TOKENS, 512, CONVX_SMEM>>>(x, gv);
    // 4: fused GEMM  (out = X @ W^T ; midd = X @ A^T)
    gemm_tpl<2048, 0><<<dim3(N_WA / BN, T / BM), 256, GEMM_SMEM>>>(
        xh, wa, out, midd, nullptr);
    // 5-8: routing finalize + LoRA operand prep
    gnorm_kernel<<<N_EXP, 256>>>(gv);
    topk_kernel<<<(T + 255) / 256, 256>>>(al);
    midw_kernel<<<T / 32, 256>>>();
    convB_kernel<<<D_OUT * N_EXP / 256, 256>>>(B);
    // 9: out += midw @ Bh^T + bias
    gemm_tpl<256, 1><<<dim3(D_OUT / BN, T / BM), 256, GEMM_SMEM>>>(
        mw, bh, out, nullptr, bb);
}